// round 7
// baseline (speedup 1.0000x reference)
#include <cuda_runtime.h>
#include <cstdint>
#include <math.h>

#define BSZ 4
#define TLEN 2048
#define CDIM 1024
#define NH 16
#define HD 64
#define BT (BSZ * TLEN)      /* 8192 */
#define N3 (3 * CDIM)        /* 3072 */

// Scratch (allocation-free rule: __device__ globals)
__device__ float g_Q[BT * CDIM];      // [B,H,T,Dh]
__device__ float g_K[BT * CDIM];
__device__ float g_V[BT * CDIM];
__device__ float g_att[BT * CDIM];    // [B,T,C]
__device__ float g_WqkvT[N3 * CDIM];  // [3072,1024]  (W_qkv^T)
__device__ float g_WprojT[CDIM * CDIM];

// ---------------------------------------------------------------------------
// Portable helpers (sm_80+ — no 'a'-suffix features)
// ---------------------------------------------------------------------------
__device__ __forceinline__ uint32_t f2tf32(float x) {
    uint32_t u;
    asm("cvt.rna.tf32.f32 %0, %1;" : "=r"(u) : "f"(x));
    return u;
}
__device__ __forceinline__ uint32_t smem_u32(const void* p) {
    uint32_t a;
    asm("{ .reg .u64 t; cvta.to.shared.u64 t, %1; cvt.u32.u64 %0, t; }"
        : "=r"(a) : "l"(p));
    return a;
}

#define MMA_TF32(d, a, b)                                                        \
    asm volatile(                                                                \
        "mma.sync.aligned.m16n8k8.row.col.f32.tf32.tf32.f32 "                    \
        "{%0,%1,%2,%3}, {%4,%5,%6,%7}, {%8,%9}, {%0,%1,%2,%3};"                  \
        : "+f"((d)[0]), "+f"((d)[1]), "+f"((d)[2]), "+f"((d)[3])                 \
        : "r"((a)[0]), "r"((a)[1]), "r"((a)[2]), "r"((a)[3]),                    \
          "r"((b)[0]), "r"((b)[1]))

#define CP_ASYNC16(smaddr, gptr)                                                 \
    asm volatile("cp.async.cg.shared.global [%0], [%1], 16;"                     \
                 :: "r"(smaddr), "l"(gptr))
#define CP_COMMIT() asm volatile("cp.async.commit_group;" ::: "memory")
#define CP_WAIT0()  asm volatile("cp.async.wait_group 0;" ::: "memory")

// ---------------------------------------------------------------------------
// One-shot weight transposes:  out[N,K] = in[K,N]^T
// ---------------------------------------------------------------------------
__global__ __launch_bounds__(256) void transpose32(const float* __restrict__ in,
                                                   float* __restrict__ out,
                                                   int R, int C) {
    __shared__ float tile[32][33];
    const int c0 = blockIdx.x * 32, r0 = blockIdx.y * 32;
    const int tx = threadIdx.x & 31, ty = threadIdx.x >> 5;
#pragma unroll
    for (int i = 0; i < 4; i++) {
        int r = ty + i * 8;
        tile[r][tx] = in[(size_t)(r0 + r) * C + c0 + tx];
    }
    __syncthreads();
#pragma unroll
    for (int i = 0; i < 4; i++) {
        int r = ty + i * 8;
        out[(size_t)(c0 + r) * R + r0 + tx] = tile[tx][r];
    }
}

// ---------------------------------------------------------------------------
// tf32 mma.sync GEMM with cp.async double-buffered pipeline.
// D[128x128] tile = A[m0:, :] * Bt[n0:, :]^T (+bias). One barrier per chunk.
// Raw fp32 lands in smem via cp.async; each thread converts its OWN chunks
// in place (same mapping as issue -> no extra barrier needed).
// MODE 0: QKV epilogue scatter -> g_Q/g_K/g_V;  MODE 1: plain out.
// ---------------------------------------------------------------------------
#define SSTR 36
#define MM_TILE (128 * SSTR)
#define MM_SMEM (4 * MM_TILE * 4)

template <int MODE>
__global__ __launch_bounds__(256, 2)
void mm_tf32(const float* __restrict__ A, const float* __restrict__ Bt,
             const float* __restrict__ bias, float* __restrict__ out) {
    extern __shared__ uint32_t gsm[];
    uint32_t* AsP[2] = {gsm, gsm + 2 * MM_TILE};
    uint32_t* BsP[2] = {gsm + MM_TILE, gsm + 3 * MM_TILE};
    const uint32_t smb = smem_u32(gsm);

    const int t = threadIdx.x;
    const int m0 = blockIdx.y * 128;
    const int n0 = blockIdx.x * 128;
    const int lane = t & 31, w = t >> 5;
    const int wr = w >> 2, wc = w & 3;

    float d[4][4][4];
#pragma unroll
    for (int i = 0; i < 4; i++)
#pragma unroll
        for (int j = 0; j < 4; j++)
#pragma unroll
            for (int e = 0; e < 4; e++) d[i][j][e] = 0.f;

    const int gr = t >> 3;             // 0..31
    const int gc4 = (t & 7) * 4;       // float offset of this thread's chunk
    const float* Ap = A + (size_t)(m0 + gr) * CDIM + gc4;
    const float* Bp = Bt + (size_t)(n0 + gr) * CDIM + gc4;

    const int ar = wr * 64 + (lane >> 2);
    const int ac = lane & 3;
    const int br = wc * 32 + (lane >> 2);

    // issue cp.async for chunk ch into buffer ch&1
#define MM_ISSUE(ch)                                                             \
    do {                                                                         \
        const int _k0 = (ch) * 32, _st = (ch) & 1;                               \
        const uint32_t _ab = smb + (_st ? 2 * MM_TILE : 0) * 4;                  \
        const uint32_t _bb = smb + (_st ? 3 * MM_TILE : MM_TILE) * 4;            \
        _Pragma("unroll")                                                        \
        for (int p = 0; p < 4; p++) {                                            \
            const int row = gr + p * 32;                                         \
            CP_ASYNC16(_ab + (row * SSTR + gc4) * 4,                             \
                       Ap + (size_t)(p * 32) * CDIM + _k0);                      \
            CP_ASYNC16(_bb + (row * SSTR + gc4) * 4,                             \
                       Bp + (size_t)(p * 32) * CDIM + _k0);                      \
        }                                                                        \
        CP_COMMIT();                                                             \
    } while (0)

    MM_ISSUE(0);

    for (int ch = 0; ch < 32; ch++) {
        const int st = ch & 1;
        uint32_t* As = AsP[st];
        uint32_t* Bs = BsP[st];

        CP_WAIT0();
        // in-place tf32 convert of this thread's own chunks
#pragma unroll
        for (int p = 0; p < 4; p++) {
            const int off = (gr + p * 32) * SSTR + gc4;
            uint4 ra = *(uint4*)&As[off];
            ra.x = f2tf32(__uint_as_float(ra.x));
            ra.y = f2tf32(__uint_as_float(ra.y));
            ra.z = f2tf32(__uint_as_float(ra.z));
            ra.w = f2tf32(__uint_as_float(ra.w));
            *(uint4*)&As[off] = ra;
            uint4 rb = *(uint4*)&Bs[off];
            rb.x = f2tf32(__uint_as_float(rb.x));
            rb.y = f2tf32(__uint_as_float(rb.y));
            rb.z = f2tf32(__uint_as_float(rb.z));
            rb.w = f2tf32(__uint_as_float(rb.w));
            *(uint4*)&Bs[off] = rb;
        }
        __syncthreads();
        if (ch < 31) MM_ISSUE(ch + 1);

#pragma unroll
        for (int ks = 0; ks < 4; ks++) {
            const int kk = ks * 8 + ac;
            uint32_t a[4][4], b[4][2];
#pragma unroll
            for (int i = 0; i < 4; i++) {
                const int r = (ar + i * 16) * SSTR;
                a[i][0] = As[r + kk];
                a[i][1] = As[r + 8 * SSTR + kk];
                a[i][2] = As[r + kk + 4];
                a[i][3] = As[r + 8 * SSTR + kk + 4];
            }
#pragma unroll
            for (int j = 0; j < 4; j++) {
                const int r = (br + j * 8) * SSTR;
                b[j][0] = Bs[r + kk];
                b[j][1] = Bs[r + kk + 4];
            }
#pragma unroll
            for (int i = 0; i < 4; i++)
#pragma unroll
                for (int j = 0; j < 4; j++) MMA_TF32(d[i][j], a[i], b[j]);
        }
    }

    const int r0 = lane >> 2, c0 = (lane & 3) * 2;
#pragma unroll
    for (int i = 0; i < 4; i++) {
        const int gmA = m0 + wr * 64 + i * 16 + r0;
        const int gmB = gmA + 8;
#pragma unroll
        for (int j = 0; j < 4; j++) {
            const int gn = n0 + wc * 32 + j * 8 + c0;
            const float bx = bias[gn], by = bias[gn + 1];
            float2 vA = make_float2(d[i][j][0] + bx, d[i][j][1] + by);
            float2 vB = make_float2(d[i][j][2] + bx, d[i][j][3] + by);
            if (MODE == 0) {
                const int which = gn >> 10;
                const int c = gn & 1023;
                const int h = c >> 6, d0 = c & 63;
                float* base = (which == 0) ? g_Q : ((which == 1) ? g_K : g_V);
                const int bA = gmA >> 11, tA = gmA & 2047;
                const int bB = gmB >> 11, tB = gmB & 2047;
                *(float2*)(base + ((size_t)(bA * NH + h) * TLEN + tA) * HD + d0) = vA;
                *(float2*)(base + ((size_t)(bB * NH + h) * TLEN + tB) * HD + d0) = vB;
            } else {
                *(float2*)(out + (size_t)gmA * CDIM + gn) = vA;
                *(float2*)(out + (size_t)gmB * CDIM + gn) = vB;
            }
        }
    }
#undef MM_ISSUE
}

// ---------------------------------------------------------------------------
// Tensor-core flash attention v4 (causal, tf32 mma.sync, cp.async pipeline).
// Block = 128 threads (4 warps), Q/K tiles 64; grid 2048, heavy-first.
// K/V double-buffered raw via cp.async; in-place tf32 convert of own chunks;
// ONE barrier per tile. V kept row-major (B-frag reads, <=2-way conflicts).
// Q frags in registers; P transposed C-frag -> A-frag via shfl.
// ---------------------------------------------------------------------------
#define SA 68
#define ATILE (64 * SA)
#define ATTN_SMEM (4 * ATILE * 4)

__global__ __launch_bounds__(128) void attn_mma() {
    extern __shared__ uint32_t smw[];
    uint32_t* KbP[2] = {smw, smw + ATILE};
    uint32_t* VbP[2] = {smw + 2 * ATILE, smw + 3 * ATILE};
    const uint32_t smb = smem_u32(smw);

    const int t = threadIdx.x;
    const int lane = t & 31, w = t >> 5;
    const int qi = (gridDim.x - 1) - blockIdx.x;  // heavy tiles first
    const int bh = blockIdx.y;
    const int q0 = qi * 64;

    const float* Qg = g_Q + (size_t)bh * TLEN * HD;
    const float* Kg = g_K + (size_t)bh * TLEN * HD;
    const float* Vg = g_V + (size_t)bh * TLEN * HD;

    const int r0w = w * 16 + (lane >> 2);
    const int lk = lane & 3;
    const int src0 = (lane & 28) + ((lane >> 1) & 1);
    const int src1 = src0 + 2;
    const bool oddl = lane & 1;

    // issue cp.async for K/V tile kt into buffer kt&1
#define KV_ISSUE(kt)                                                             \
    do {                                                                         \
        const int _k0 = (kt) * 64, _st = (kt) & 1;                               \
        const uint32_t _kb = smb + (_st ? ATILE : 0) * 4;                        \
        const uint32_t _vb = smb + ((_st ? 3 : 2) * ATILE) * 4;                  \
        _Pragma("unroll")                                                        \
        for (int it = 0; it < 8; it++) {                                         \
            const int i = it * 128 + t;                                          \
            const int row = i >> 4, c4 = (i & 15) * 4;                           \
            CP_ASYNC16(_kb + (row * SA + c4) * 4,                                \
                       Kg + (size_t)(_k0 + row) * HD + c4);                      \
            CP_ASYNC16(_vb + (row * SA + c4) * 4,                                \
                       Vg + (size_t)(_k0 + row) * HD + c4);                      \
        }                                                                        \
        CP_COMMIT();                                                             \
    } while (0)

    KV_ISSUE(0);

    // Stage Q through Kb[1] (free until tile-1 cp.async, which is issued
    // after the iter-0 barrier, i.e. after every thread's qf loads).
    {
        uint32_t* Qs = KbP[1];
#pragma unroll
        for (int it = 0; it < 8; it++) {
            const int i = it * 128 + t;
            const int row = i >> 4, c4 = (i & 15) * 4;
            float4 v = *(const float4*)(Qg + (size_t)(q0 + row) * HD + c4);
            uint4 u;
            u.x = f2tf32(v.x * 0.125f);
            u.y = f2tf32(v.y * 0.125f);
            u.z = f2tf32(v.z * 0.125f);
            u.w = f2tf32(v.w * 0.125f);
            *(uint4*)&Qs[row * SA + c4] = u;
        }
    }
    __syncthreads();
    uint32_t qf[8][4];
    {
        const int abase = r0w * SA;
        uint32_t* Qs = KbP[1];
#pragma unroll
        for (int ks = 0; ks < 8; ks++) {
            const int kk = ks * 8 + lk;
            qf[ks][0] = Qs[abase + kk];
            qf[ks][1] = Qs[abase + 8 * SA + kk];
            qf[ks][2] = Qs[abase + kk + 4];
            qf[ks][3] = Qs[abase + 8 * SA + kk + 4];
        }
    }

    float o[8][4];
#pragma unroll
    for (int j = 0; j < 8; j++)
#pragma unroll
        for (int e = 0; e < 4; e++) o[j][e] = 0.f;
    float m0 = -1e30f, m1 = -1e30f, l0 = 0.f, l1 = 0.f;

    for (int kt = 0; kt <= qi; kt++) {
        uint32_t* cK = KbP[kt & 1];
        uint32_t* cV = VbP[kt & 1];

        CP_WAIT0();
        // in-place tf32 convert of this thread's own chunks
#pragma unroll
        for (int it = 0; it < 8; it++) {
            const int i = it * 128 + t;
            const int off = (i >> 4) * SA + (i & 15) * 4;
            uint4 rk = *(uint4*)&cK[off];
            rk.x = f2tf32(__uint_as_float(rk.x));
            rk.y = f2tf32(__uint_as_float(rk.y));
            rk.z = f2tf32(__uint_as_float(rk.z));
            rk.w = f2tf32(__uint_as_float(rk.w));
            *(uint4*)&cK[off] = rk;
            uint4 rv = *(uint4*)&cV[off];
            rv.x = f2tf32(__uint_as_float(rv.x));
            rv.y = f2tf32(__uint_as_float(rv.y));
            rv.z = f2tf32(__uint_as_float(rv.z));
            rv.w = f2tf32(__uint_as_float(rv.w));
            *(uint4*)&cV[off] = rv;
        }
        __syncthreads();
        if (kt < qi) KV_ISSUE(kt + 1);

        // S = (Q*scale) @ K^T   (Q from registers)
        float s[8][4];
#pragma unroll
        for (int j = 0; j < 8; j++)
#pragma unroll
            for (int e = 0; e < 4; e++) s[j][e] = 0.f;
#pragma unroll
        for (int ks = 0; ks < 8; ks++) {
            const int kk = ks * 8 + lk;
#pragma unroll
            for (int j = 0; j < 8; j++) {
                const int r = (j * 8 + (lane >> 2)) * SA;
                uint32_t b[2];
                b[0] = cK[r + kk];
                b[1] = cK[r + kk + 4];
                MMA_TF32(s[j], qf[ks], b);
            }
        }

        // Causal mask (diagonal tile only; uniform branch)
        if (kt == qi) {
            const int k0 = kt * 64;
            const int gr0 = q0 + r0w, gr1 = gr0 + 8;
#pragma unroll
            for (int j = 0; j < 8; j++) {
                const int c = k0 + j * 8 + 2 * lk;
                if (c > gr0) s[j][0] = -1e30f;
                if (c + 1 > gr0) s[j][1] = -1e30f;
                if (c > gr1) s[j][2] = -1e30f;
                if (c + 1 > gr1) s[j][3] = -1e30f;
            }
        }

        // Online softmax
        float tm0 = -1e30f, tm1 = -1e30f;
#pragma unroll
        for (int j = 0; j < 8; j++) {
            tm0 = fmaxf(tm0, fmaxf(s[j][0], s[j][1]));
            tm1 = fmaxf(tm1, fmaxf(s[j][2], s[j][3]));
        }
        tm0 = fmaxf(tm0, __shfl_xor_sync(0xffffffffu, tm0, 1));
        tm0 = fmaxf(tm0, __shfl_xor_sync(0xffffffffu, tm0, 2));
        tm1 = fmaxf(tm1, __shfl_xor_sync(0xffffffffu, tm1, 1));
        tm1 = fmaxf(tm1, __shfl_xor_sync(0xffffffffu, tm1, 2));

        const float mn0 = fmaxf(m0, tm0), mn1 = fmaxf(m1, tm1);
        const float al0 = __expf(m0 - mn0), al1 = __expf(m1 - mn1);
        m0 = mn0; m1 = mn1;

        float rs0 = 0.f, rs1 = 0.f;
#pragma unroll
        for (int j = 0; j < 8; j++) {
            s[j][0] = __expf(s[j][0] - mn0); rs0 += s[j][0];
            s[j][1] = __expf(s[j][1] - mn0); rs0 += s[j][1];
            s[j][2] = __expf(s[j][2] - mn1); rs1 += s[j][2];
            s[j][3] = __expf(s[j][3] - mn1); rs1 += s[j][3];
        }
        rs0 += __shfl_xor_sync(0xffffffffu, rs0, 1);
        rs0 += __shfl_xor_sync(0xffffffffu, rs0, 2);
        rs1 += __shfl_xor_sync(0xffffffffu, rs1, 1);
        rs1 += __shfl_xor_sync(0xffffffffu, rs1, 2);
        l0 = l0 * al0 + rs0;
        l1 = l1 * al1 + rs1;
#pragma unroll
        for (int j = 0; j < 8; j++) {
            o[j][0] *= al0; o[j][1] *= al0;
            o[j][2] *= al1; o[j][3] *= al1;
        }

        // O += P @ V  (P via shfl transpose; V row-major: B(k=key, n=d))
#pragma unroll
        for (int ks = 0; ks < 8; ks++) {
            float v00 = __shfl_sync(0xffffffffu, s[ks][0], src0);
            float v01 = __shfl_sync(0xffffffffu, s[ks][1], src0);
            float v20 = __shfl_sync(0xffffffffu, s[ks][2], src0);
            float v21 = __shfl_sync(0xffffffffu, s[ks][3], src0);
            float v0b = __shfl_sync(0xffffffffu, s[ks][0], src1);
            float v1b = __shfl_sync(0xffffffffu, s[ks][1], src1);
            float v2b = __shfl_sync(0xffffffffu, s[ks][2], src1);
            float v3b = __shfl_sync(0xffffffffu, s[ks][3], src1);
            uint32_t a[4];
            a[0] = f2tf32(oddl ? v01 : v00);
            a[1] = f2tf32(oddl ? v21 : v20);
            a[2] = f2tf32(oddl ? v1b : v0b);
            a[3] = f2tf32(oddl ? v3b : v2b);
            const int krow0 = (ks * 8 + lk) * SA;
            const int krow1 = (ks * 8 + lk + 4) * SA;
#pragma unroll
            for (int j = 0; j < 8; j++) {
                const int dcol = j * 8 + (lane >> 2);
                uint32_t b[2];
                b[0] = cV[krow0 + dcol];
                b[1] = cV[krow1 + dcol];
                MMA_TF32(o[j], a, b);
            }
        }
    }

    // Epilogue -> g_att [B,T,C]
    const float inv0 = 1.f / l0, inv1 = 1.f / l1;
    const int b = bh >> 4, h = bh & 15;
    const int gr0 = q0 + r0w, gr1 = gr0 + 8;
    float* o0 = g_att + ((size_t)(b * TLEN + gr0)) * CDIM + h * HD;
    float* o1 = g_att + ((size_t)(b * TLEN + gr1)) * CDIM + h * HD;
#pragma unroll
    for (int j = 0; j < 8; j++) {
        const int c = j * 8 + 2 * lk;
        *(float2*)(o0 + c) = make_float2(o[j][0] * inv0, o[j][1] * inv0);
        *(float2*)(o1 + c) = make_float2(o[j][2] * inv1, o[j][3] * inv1);
    }
#undef KV_ISSUE
}

// ---------------------------------------------------------------------------
extern "C" void kernel_launch(void* const* d_in, const int* in_sizes, int n_in,
                              void* d_out, int out_size) {
    const float* x = (const float*)d_in[0];
    const float* W_qkv = (const float*)d_in[1];
    const float* b_qkv = (const float*)d_in[2];
    const float* W_proj = (const float*)d_in[3];
    const float* b_proj = (const float*)d_in[4];
    float* out = (float*)d_out;

    float *wqkvT = nullptr, *wprojT = nullptr, *attp = nullptr;
    cudaGetSymbolAddress((void**)&wqkvT, g_WqkvT);
    cudaGetSymbolAddress((void**)&wprojT, g_WprojT);
    cudaGetSymbolAddress((void**)&attp, g_att);

    cudaFuncSetAttribute(attn_mma, cudaFuncAttributeMaxDynamicSharedMemorySize,
                         ATTN_SMEM);
    cudaFuncSetAttribute(mm_tf32<0>, cudaFuncAttributeMaxDynamicSharedMemorySize,
                         MM_SMEM);
    cudaFuncSetAttribute(mm_tf32<1>, cudaFuncAttributeMaxDynamicSharedMemorySize,
                         MM_SMEM);

    transpose32<<<dim3(N3 / 32, CDIM / 32), 256>>>(W_qkv, wqkvT, CDIM, N3);
    transpose32<<<dim3(CDIM / 32, CDIM / 32), 256>>>(W_proj, wprojT, CDIM, CDIM);

    mm_tf32<0><<<dim3(N3 / 128, BT / 128), 256, MM_SMEM>>>(x, wqkvT, b_qkv, nullptr);

    attn_mma<<<dim3(TLEN / 64, BSZ * NH), 128, ATTN_SMEM>>>();

    mm_tf32<1><<<dim3(CDIM / 128, BT / 128), 256, MM_SMEM>>>(attp, wprojT, b_proj, out);
}

// round 8
// speedup vs baseline: 1.0054x; 1.0054x over previous
#include <cuda_runtime.h>
#include <cstdint>
#include <math.h>

#define BSZ 4
#define TLEN 2048
#define CDIM 1024
#define NH 16
#define HD 64
#define BT (BSZ * TLEN)      /* 8192 */
#define N3 (3 * CDIM)        /* 3072 */

// Scratch (allocation-free rule: __device__ globals)
__device__ float g_Q[BT * CDIM];      // [B,H,T,Dh]
__device__ float g_K[BT * CDIM];
__device__ float g_V[BT * CDIM];
__device__ float g_att[BT * CDIM];    // [B,T,C]
__device__ float g_WqkvT[N3 * CDIM];  // [3072,1024]  (W_qkv^T)
__device__ float g_WprojT[CDIM * CDIM];

// ---------------------------------------------------------------------------
// Portable tensor-core helpers (sm_80+ mma.sync — no 'a'-suffix features)
// ---------------------------------------------------------------------------
__device__ __forceinline__ uint32_t f2tf32(float x) {
    uint32_t u;
    asm("cvt.rna.tf32.f32 %0, %1;" : "=r"(u) : "f"(x));
    return u;
}

#define MMA_TF32(d, a, b)                                                        \
    asm volatile(                                                                \
        "mma.sync.aligned.m16n8k8.row.col.f32.tf32.tf32.f32 "                    \
        "{%0,%1,%2,%3}, {%4,%5,%6,%7}, {%8,%9}, {%0,%1,%2,%3};"                  \
        : "+f"((d)[0]), "+f"((d)[1]), "+f"((d)[2]), "+f"((d)[3])                 \
        : "r"((a)[0]), "r"((a)[1]), "r"((a)[2]), "r"((a)[3]),                    \
          "r"((b)[0]), "r"((b)[1]))

// ---------------------------------------------------------------------------
// One-shot weight transposes:  out[N,K] = in[K,N]^T
// ---------------------------------------------------------------------------
__global__ __launch_bounds__(256) void transpose32(const float* __restrict__ in,
                                                   float* __restrict__ out,
                                                   int R, int C) {
    __shared__ float tile[32][33];
    const int c0 = blockIdx.x * 32, r0 = blockIdx.y * 32;
    const int tx = threadIdx.x & 31, ty = threadIdx.x >> 5;
#pragma unroll
    for (int i = 0; i < 4; i++) {
        int r = ty + i * 8;
        tile[r][tx] = in[(size_t)(r0 + r) * C + c0 + tx];
    }
    __syncthreads();
#pragma unroll
    for (int i = 0; i < 4; i++) {
        int r = ty + i * 8;
        out[(size_t)(c0 + r) * R + r0 + tx] = tile[tx][r];
    }
}

// ---------------------------------------------------------------------------
// tf32 mma.sync GEMM, pair-interleaved smem: element k and k+4 of each row are
// adjacent, so every fragment load is one LDS.64. Row stride 40 floats
// (stride_8B = 20 ≡ 4 mod 16) -> conflict-free 16-lane LDS.64 phases.
// MODE 0: QKV epilogue scatter -> g_Q/g_K/g_V;  MODE 1: plain out.
// ---------------------------------------------------------------------------
#define RS 40   /* floats per row: 32 data (as 16 pairs) + 8 pad */

template <int MODE>
__global__ __launch_bounds__(256, 2)
void mm_tf32(const float* __restrict__ A, const float* __restrict__ Bt,
             const float* __restrict__ bias, float* __restrict__ out) {
    __shared__ __align__(16) uint32_t As[128 * RS];
    __shared__ __align__(16) uint32_t Bs[128 * RS];

    const int t = threadIdx.x;
    const int m0 = blockIdx.y * 128;
    const int n0 = blockIdx.x * 128;
    const int lane = t & 31, w = t >> 5;
    const int wr = w >> 2, wc = w & 3;

    float d[4][4][4];
#pragma unroll
    for (int i = 0; i < 4; i++)
#pragma unroll
        for (int j = 0; j < 4; j++)
#pragma unroll
            for (int e = 0; e < 4; e++) d[i][j][e] = 0.f;

    const int gr = t >> 3;             // 0..31
    const int gc4 = (t & 7) * 4;       // k offset of this thread's float4
    const float* Ap = A + (size_t)(m0 + gr) * CDIM + gc4;
    const float* Bp = Bt + (size_t)(n0 + gr) * CDIM + gc4;
    // pair-store base: k = dg*8 + c pairs with k+4; addr = row*RS + dg*8 + 2c + half
    const int soff = ((gc4 >> 3) * 8) + ((gc4 >> 2) & 1);

    const int ar = wr * 64 + (lane >> 2);
    const int ac = lane & 3;
    const int br = wc * 32 + (lane >> 2);

    for (int k0 = 0; k0 < CDIM; k0 += 32) {
        __syncthreads();
#pragma unroll
        for (int p = 0; p < 4; p++) {
            const int row = gr + p * 32;
            float4 va = *(const float4*)(Ap + (size_t)(p * 32) * CDIM + k0);
            float4 vb = *(const float4*)(Bp + (size_t)(p * 32) * CDIM + k0);
            const int off = row * RS + soff;
            As[off + 0] = f2tf32(va.x); As[off + 2] = f2tf32(va.y);
            As[off + 4] = f2tf32(va.z); As[off + 6] = f2tf32(va.w);
            Bs[off + 0] = f2tf32(vb.x); Bs[off + 2] = f2tf32(vb.y);
            Bs[off + 4] = f2tf32(vb.z); Bs[off + 6] = f2tf32(vb.w);
        }
        __syncthreads();

#pragma unroll
        for (int ks = 0; ks < 4; ks++) {
            const int koff = ks * 8 + 2 * ac;
            uint32_t a[4][4], b[4][2];
#pragma unroll
            for (int i = 0; i < 4; i++) {
                const int r = (ar + i * 16) * RS;
                uint2 p0 = *(const uint2*)&As[r + koff];
                uint2 p1 = *(const uint2*)&As[r + 8 * RS + koff];
                a[i][0] = p0.x; a[i][2] = p0.y;
                a[i][1] = p1.x; a[i][3] = p1.y;
            }
#pragma unroll
            for (int j = 0; j < 4; j++) {
                const int r = (br + j * 8) * RS;
                uint2 pb = *(const uint2*)&Bs[r + koff];
                b[j][0] = pb.x; b[j][1] = pb.y;
            }
#pragma unroll
            for (int i = 0; i < 4; i++)
#pragma unroll
                for (int j = 0; j < 4; j++) MMA_TF32(d[i][j], a[i], b[j]);
        }
    }

    const int r0 = lane >> 2, c0 = (lane & 3) * 2;
#pragma unroll
    for (int i = 0; i < 4; i++) {
        const int gmA = m0 + wr * 64 + i * 16 + r0;
        const int gmB = gmA + 8;
#pragma unroll
        for (int j = 0; j < 4; j++) {
            const int gn = n0 + wc * 32 + j * 8 + c0;
            const float bx = bias[gn], by = bias[gn + 1];
            float2 vA = make_float2(d[i][j][0] + bx, d[i][j][1] + by);
            float2 vB = make_float2(d[i][j][2] + bx, d[i][j][3] + by);
            if (MODE == 0) {
                const int which = gn >> 10;
                const int c = gn & 1023;
                const int h = c >> 6, d0 = c & 63;
                float* base = (which == 0) ? g_Q : ((which == 1) ? g_K : g_V);
                const int bA = gmA >> 11, tA = gmA & 2047;
                const int bB = gmB >> 11, tB = gmB & 2047;
                *(float2*)(base + ((size_t)(bA * NH + h) * TLEN + tA) * HD + d0) = vA;
                *(float2*)(base + ((size_t)(bB * NH + h) * TLEN + tB) * HD + d0) = vB;
            } else {
                *(float2*)(out + (size_t)gmA * CDIM + gn) = vA;
                *(float2*)(out + (size_t)gmB * CDIM + gn) = vB;
            }
        }
    }
}

// ---------------------------------------------------------------------------
// Tensor-core flash attention v5 (causal, tf32 mma.sync), pair layouts.
// Block = 128 threads (4 warps), Q/K tiles 64; grid 2048, heavy-first.
// K pair layout along d (stride 72): S-loop B-frag = 1 LDS.64, conflict-free.
// V pair layout along keys (stride 136): PV B-frag = 1 LDS.64, conflict-free.
// Q frags in registers; P transposed C-frag -> A-frag via shfl. 2 barriers/tile.
// ---------------------------------------------------------------------------
#define KSTR 72    /* floats per key row: 64 data (32 pairs) + 8 pad */
#define VSTR 136   /* floats per key-pair row: 128 data (64 d x pair) + 8 pad */
#define ATTN_SMEM ((64 * KSTR + 32 * VSTR) * 4)

__global__ __launch_bounds__(128) void attn_mma() {
    extern __shared__ uint32_t smw[];
    uint32_t* Ks = smw;               // 64 x KSTR (pair-d), also Q staging
    uint32_t* Vp = smw + 64 * KSTR;   // 32 x VSTR (pair-key per d)

    const int t = threadIdx.x;
    const int lane = t & 31, w = t >> 5;
    const int qi = (gridDim.x - 1) - blockIdx.x;  // heavy tiles first
    const int bh = blockIdx.y;
    const int q0 = qi * 64;

    const float* Qg = g_Q + (size_t)bh * TLEN * HD;
    const float* Kg = g_K + (size_t)bh * TLEN * HD;
    const float* Vg = g_V + (size_t)bh * TLEN * HD;

    const int r0w = w * 16 + (lane >> 2);
    const int lk = lane & 3;
    const int src0 = (lane & 28) + ((lane >> 1) & 1);
    const int src1 = src0 + 2;
    const bool oddl = lane & 1;

    // Stage Q into Ks (pair layout), hoist fragments to registers.
    for (int i = t; i < 64 * 16; i += 128) {
        const int row = i >> 4, c4 = (i & 15) * 4;
        const int off = row * KSTR + ((c4 >> 3) * 8) + ((c4 >> 2) & 1);
        float4 v = *(const float4*)(Qg + (size_t)(q0 + row) * HD + c4);
        Ks[off + 0] = f2tf32(v.x * 0.125f);
        Ks[off + 2] = f2tf32(v.y * 0.125f);
        Ks[off + 4] = f2tf32(v.z * 0.125f);
        Ks[off + 6] = f2tf32(v.w * 0.125f);
    }
    __syncthreads();
    uint32_t qf[8][4];
#pragma unroll
    for (int ks = 0; ks < 8; ks++) {
        const int koff = ks * 8 + 2 * lk;
        uint2 p0 = *(const uint2*)&Ks[r0w * KSTR + koff];
        uint2 p1 = *(const uint2*)&Ks[(r0w + 8) * KSTR + koff];
        qf[ks][0] = p0.x; qf[ks][2] = p0.y;
        qf[ks][1] = p1.x; qf[ks][3] = p1.y;
    }

    float o[8][4];
#pragma unroll
    for (int j = 0; j < 8; j++)
#pragma unroll
        for (int e = 0; e < 4; e++) o[j][e] = 0.f;
    float m0 = -1e30f, m1 = -1e30f, l0 = 0.f, l1 = 0.f;

    for (int kt = 0; kt <= qi; kt++) {
        const int k0 = kt * 64;
        __syncthreads();  // Ks/Vp free of prior readers (incl. qf loads)
        for (int i = t; i < 64 * 16; i += 128) {
            const int row = i >> 4, c4 = (i & 15) * 4;
            // K: pair along d
            const int koff = row * KSTR + ((c4 >> 3) * 8) + ((c4 >> 2) & 1);
            float4 kv = *(const float4*)(Kg + (size_t)(k0 + row) * HD + c4);
            Ks[koff + 0] = f2tf32(kv.x);
            Ks[koff + 2] = f2tf32(kv.y);
            Ks[koff + 4] = f2tf32(kv.z);
            Ks[koff + 6] = f2tf32(kv.w);
            // V: pair along keys (row c pairs with row c+4 within key-group)
            const int voff = ((row >> 3) * 4 + (row & 3)) * VSTR + c4 * 2 +
                             ((row >> 2) & 1);
            float4 vv = *(const float4*)(Vg + (size_t)(k0 + row) * HD + c4);
            Vp[voff + 0] = f2tf32(vv.x);
            Vp[voff + 2] = f2tf32(vv.y);
            Vp[voff + 4] = f2tf32(vv.z);
            Vp[voff + 6] = f2tf32(vv.w);
        }
        __syncthreads();

        // S = (Q*scale) @ K^T   (Q from registers; K pairs via LDS.64)
        float s[8][4];
#pragma unroll
        for (int j = 0; j < 8; j++)
#pragma unroll
            for (int e = 0; e < 4; e++) s[j][e] = 0.f;
#pragma unroll
        for (int ks = 0; ks < 8; ks++) {
            const int koff = ks * 8 + 2 * lk;
#pragma unroll
            for (int j = 0; j < 8; j++) {
                uint2 pb = *(const uint2*)&Ks[(j * 8 + (lane >> 2)) * KSTR + koff];
                uint32_t b[2] = {pb.x, pb.y};
                MMA_TF32(s[j], qf[ks], b);
            }
        }

        // Causal mask (diagonal tile only; uniform branch)
        if (kt == qi) {
            const int gr0 = q0 + r0w, gr1 = gr0 + 8;
#pragma unroll
            for (int j = 0; j < 8; j++) {
                const int c = k0 + j * 8 + 2 * lk;
                if (c > gr0) s[j][0] = -1e30f;
                if (c + 1 > gr0) s[j][1] = -1e30f;
                if (c > gr1) s[j][2] = -1e30f;
                if (c + 1 > gr1) s[j][3] = -1e30f;
            }
        }

        // Online softmax
        float tm0 = -1e30f, tm1 = -1e30f;
#pragma unroll
        for (int j = 0; j < 8; j++) {
            tm0 = fmaxf(tm0, fmaxf(s[j][0], s[j][1]));
            tm1 = fmaxf(tm1, fmaxf(s[j][2], s[j][3]));
        }
        tm0 = fmaxf(tm0, __shfl_xor_sync(0xffffffffu, tm0, 1));
        tm0 = fmaxf(tm0, __shfl_xor_sync(0xffffffffu, tm0, 2));
        tm1 = fmaxf(tm1, __shfl_xor_sync(0xffffffffu, tm1, 1));
        tm1 = fmaxf(tm1, __shfl_xor_sync(0xffffffffu, tm1, 2));

        const float mn0 = fmaxf(m0, tm0), mn1 = fmaxf(m1, tm1);
        const float al0 = __expf(m0 - mn0), al1 = __expf(m1 - mn1);
        m0 = mn0; m1 = mn1;

        float rs0 = 0.f, rs1 = 0.f;
#pragma unroll
        for (int j = 0; j < 8; j++) {
            s[j][0] = __expf(s[j][0] - mn0); rs0 += s[j][0];
            s[j][1] = __expf(s[j][1] - mn0); rs0 += s[j][1];
            s[j][2] = __expf(s[j][2] - mn1); rs1 += s[j][2];
            s[j][3] = __expf(s[j][3] - mn1); rs1 += s[j][3];
        }
        rs0 += __shfl_xor_sync(0xffffffffu, rs0, 1);
        rs0 += __shfl_xor_sync(0xffffffffu, rs0, 2);
        rs1 += __shfl_xor_sync(0xffffffffu, rs1, 1);
        rs1 += __shfl_xor_sync(0xffffffffu, rs1, 2);
        l0 = l0 * al0 + rs0;
        l1 = l1 * al1 + rs1;
#pragma unroll
        for (int j = 0; j < 8; j++) {
            o[j][0] *= al0; o[j][1] *= al0;
            o[j][2] *= al1; o[j][3] *= al1;
        }

        // O += P @ V  (P via shfl transpose; V pairs via LDS.64)
#pragma unroll
        for (int ks = 0; ks < 8; ks++) {
            float v00 = __shfl_sync(0xffffffffu, s[ks][0], src0);
            float v01 = __shfl_sync(0xffffffffu, s[ks][1], src0);
            float v20 = __shfl_sync(0xffffffffu, s[ks][2], src0);
            float v21 = __shfl_sync(0xffffffffu, s[ks][3], src0);
            float v0b = __shfl_sync(0xffffffffu, s[ks][0], src1);
            float v1b = __shfl_sync(0xffffffffu, s[ks][1], src1);
            float v2b = __shfl_sync(0xffffffffu, s[ks][2], src1);
            float v3b = __shfl_sync(0xffffffffu, s[ks][3], src1);
            uint32_t a[4];
            a[0] = f2tf32(oddl ? v01 : v00);
            a[1] = f2tf32(oddl ? v21 : v20);
            a[2] = f2tf32(oddl ? v1b : v0b);
            a[3] = f2tf32(oddl ? v3b : v2b);
            const int vrow = (ks * 4 + lk) * VSTR;
#pragma unroll
            for (int j = 0; j < 8; j++) {
                uint2 pv = *(const uint2*)&Vp[vrow + (j * 8 + (lane >> 2)) * 2];
                uint32_t b[2] = {pv.x, pv.y};
                MMA_TF32(o[j], a, b);
            }
        }
    }

    // Epilogue -> g_att [B,T,C]
    const float inv0 = 1.f / l0, inv1 = 1.f / l1;
    const int b = bh >> 4, h = bh & 15;
    const int gr0 = q0 + r0w, gr1 = gr0 + 8;
    float* o0 = g_att + ((size_t)(b * TLEN + gr0)) * CDIM + h * HD;
    float* o1 = g_att + ((size_t)(b * TLEN + gr1)) * CDIM + h * HD;
#pragma unroll
    for (int j = 0; j < 8; j++) {
        const int c = j * 8 + 2 * lk;
        *(float2*)(o0 + c) = make_float2(o[j][0] * inv0, o[j][1] * inv0);
        *(float2*)(o1 + c) = make_float2(o[j][2] * inv1, o[j][3] * inv1);
    }
}

// ---------------------------------------------------------------------------
extern "C" void kernel_launch(void* const* d_in, const int* in_sizes, int n_in,
                              void* d_out, int out_size) {
    const float* x = (const float*)d_in[0];
    const float* W_qkv = (const float*)d_in[1];
    const float* b_qkv = (const float*)d_in[2];
    const float* W_proj = (const float*)d_in[3];
    const float* b_proj = (const float*)d_in[4];
    float* out = (float*)d_out;

    float *wqkvT = nullptr, *wprojT = nullptr, *attp = nullptr;
    cudaGetSymbolAddress((void**)&wqkvT, g_WqkvT);
    cudaGetSymbolAddress((void**)&wprojT, g_WprojT);
    cudaGetSymbolAddress((void**)&attp, g_att);

    cudaFuncSetAttribute(attn_mma, cudaFuncAttributeMaxDynamicSharedMemorySize,
                         ATTN_SMEM);

    transpose32<<<dim3(N3 / 32, CDIM / 32), 256>>>(W_qkv, wqkvT, CDIM, N3);
    transpose32<<<dim3(CDIM / 32, CDIM / 32), 256>>>(W_proj, wprojT, CDIM, CDIM);

    mm_tf32<0><<<dim3(N3 / 128, BT / 128), 256>>>(x, wqkvT, b_qkv, nullptr);

    attn_mma<<<dim3(TLEN / 64, BSZ * NH), 128, ATTN_SMEM>>>();

    mm_tf32<1><<<dim3(CDIM / 128, BT / 128), 256>>>(attp, wprojT, b_proj, out);
}

// round 9
// speedup vs baseline: 1.2519x; 1.2452x over previous
#include <cuda_runtime.h>
#include <cstdint>
#include <math.h>

#define BSZ 4
#define TLEN 2048
#define CDIM 1024
#define NH 16
#define HD 64
#define BT (BSZ * TLEN)      /* 8192 */
#define N3 (3 * CDIM)        /* 3072 */

// Scratch (allocation-free rule: __device__ globals)
__device__ float g_Q[BT * CDIM];      // [B,H,T,Dh]
__device__ float g_K[BT * CDIM];
__device__ float g_V[BT * CDIM];
__device__ float g_att[BT * CDIM];    // [B,T,C]
__device__ float g_WqkvT[N3 * CDIM];  // [3072,1024]  (W_qkv^T)
__device__ float g_WprojT[CDIM * CDIM];

// ---------------------------------------------------------------------------
// Portable tensor-core helpers (sm_80+ mma.sync — no 'a'-suffix features)
// ---------------------------------------------------------------------------
__device__ __forceinline__ uint32_t f2tf32(float x) {
    uint32_t u;
    asm("cvt.rna.tf32.f32 %0, %1;" : "=r"(u) : "f"(x));
    return u;
}

#define MMA_TF32(d, a, b)                                                        \
    asm volatile(                                                                \
        "mma.sync.aligned.m16n8k8.row.col.f32.tf32.tf32.f32 "                    \
        "{%0,%1,%2,%3}, {%4,%5,%6,%7}, {%8,%9}, {%0,%1,%2,%3};"                  \
        : "+f"((d)[0]), "+f"((d)[1]), "+f"((d)[2]), "+f"((d)[3])                 \
        : "r"((a)[0]), "r"((a)[1]), "r"((a)[2]), "r"((a)[3]),                    \
          "r"((b)[0]), "r"((b)[1]))

// ---------------------------------------------------------------------------
// One-shot weight transposes:  out[N,K] = in[K,N]^T
// ---------------------------------------------------------------------------
__global__ __launch_bounds__(256) void transpose32(const float* __restrict__ in,
                                                   float* __restrict__ out,
                                                   int R, int C) {
    __shared__ float tile[32][33];
    const int c0 = blockIdx.x * 32, r0 = blockIdx.y * 32;
    const int tx = threadIdx.x & 31, ty = threadIdx.x >> 5;
#pragma unroll
    for (int i = 0; i < 4; i++) {
        int r = ty + i * 8;
        tile[r][tx] = in[(size_t)(r0 + r) * C + c0 + tx];
    }
    __syncthreads();
#pragma unroll
    for (int i = 0; i < 4; i++) {
        int r = ty + i * 8;
        out[(size_t)(c0 + r) * R + r0 + tx] = tile[tx][r];
    }
}

// ---------------------------------------------------------------------------
// tf32 mma.sync GEMM, double-buffered smem, ONE barrier per K chunk.
// Layout/compute identical to the proven R6 kernel (SSTR=36, conflict-free);
// only the buffering changed. Safety: at sync(ch) all warps finished
// compute(ch-1), so STS(ch+1) into buffer (ch-1)&1 cannot race.
// MODE 0: QKV epilogue scatter -> g_Q/g_K/g_V;  MODE 1: plain out.
// ---------------------------------------------------------------------------
#define SSTR 36
#define MMT (128 * SSTR)
#define MM_SMEM (4 * MMT * 4)

template <int MODE>
__global__ __launch_bounds__(256, 2)
void mm_tf32(const float* __restrict__ A, const float* __restrict__ Bt,
             const float* __restrict__ bias, float* __restrict__ out) {
    extern __shared__ uint32_t gsm[];   // [A0 | B0 | A1 | B1]

    const int t = threadIdx.x;
    const int m0 = blockIdx.y * 128;
    const int n0 = blockIdx.x * 128;
    const int lane = t & 31, w = t >> 5;
    const int wr = w >> 2, wc = w & 3;

    float d[4][4][4];
#pragma unroll
    for (int i = 0; i < 4; i++)
#pragma unroll
        for (int j = 0; j < 4; j++)
#pragma unroll
            for (int e = 0; e < 4; e++) d[i][j][e] = 0.f;

    const int gr = t >> 3;
    const int gc4 = (t & 7) * 4;
    const float* Ap = A + (size_t)(m0 + gr) * CDIM + gc4;
    const float* Bp = Bt + (size_t)(n0 + gr) * CDIM + gc4;

    const int ar = wr * 64 + (lane >> 2);
    const int ac = lane & 3;
    const int br = wc * 32 + (lane >> 2);

    for (int k0 = 0; k0 < CDIM; k0 += 32) {
        const int st = (k0 >> 5) & 1;
        uint32_t* As = gsm + st * 2 * MMT;
        uint32_t* Bs = As + MMT;

#pragma unroll
        for (int p = 0; p < 4; p++) {
            const int row = gr + p * 32;
            float4 va = *(const float4*)(Ap + (size_t)(p * 32) * CDIM + k0);
            float4 vb = *(const float4*)(Bp + (size_t)(p * 32) * CDIM + k0);
            uint32_t* ad = &As[row * SSTR + gc4];
            uint32_t* bd = &Bs[row * SSTR + gc4];
            ad[0] = f2tf32(va.x); ad[1] = f2tf32(va.y);
            ad[2] = f2tf32(va.z); ad[3] = f2tf32(va.w);
            bd[0] = f2tf32(vb.x); bd[1] = f2tf32(vb.y);
            bd[2] = f2tf32(vb.z); bd[3] = f2tf32(vb.w);
        }
        __syncthreads();

#pragma unroll
        for (int ks = 0; ks < 4; ks++) {
            const int kk = ks * 8 + ac;
            uint32_t a[4][4], b[4][2];
#pragma unroll
            for (int i = 0; i < 4; i++) {
                const int r = (ar + i * 16) * SSTR;
                a[i][0] = As[r + kk];
                a[i][1] = As[r + 8 * SSTR + kk];
                a[i][2] = As[r + kk + 4];
                a[i][3] = As[r + 8 * SSTR + kk + 4];
            }
#pragma unroll
            for (int j = 0; j < 4; j++) {
                const int r = (br + j * 8) * SSTR;
                b[j][0] = Bs[r + kk];
                b[j][1] = Bs[r + kk + 4];
            }
#pragma unroll
            for (int i = 0; i < 4; i++)
#pragma unroll
                for (int j = 0; j < 4; j++) MMA_TF32(d[i][j], a[i], b[j]);
        }
    }

    const int r0 = lane >> 2, c0 = (lane & 3) * 2;
#pragma unroll
    for (int i = 0; i < 4; i++) {
        const int gmA = m0 + wr * 64 + i * 16 + r0;
        const int gmB = gmA + 8;
#pragma unroll
        for (int j = 0; j < 4; j++) {
            const int gn = n0 + wc * 32 + j * 8 + c0;
            const float bx = bias[gn], by = bias[gn + 1];
            float2 vA = make_float2(d[i][j][0] + bx, d[i][j][1] + by);
            float2 vB = make_float2(d[i][j][2] + bx, d[i][j][3] + by);
            if (MODE == 0) {
                const int which = gn >> 10;
                const int c = gn & 1023;
                const int h = c >> 6, d0 = c & 63;
                float* base = (which == 0) ? g_Q : ((which == 1) ? g_K : g_V);
                const int bA = gmA >> 11, tA = gmA & 2047;
                const int bB = gmB >> 11, tB = gmB & 2047;
                *(float2*)(base + ((size_t)(bA * NH + h) * TLEN + tA) * HD + d0) = vA;
                *(float2*)(base + ((size_t)(bB * NH + h) * TLEN + tB) * HD + d0) = vB;
            } else {
                *(float2*)(out + (size_t)gmA * CDIM + gn) = vA;
                *(float2*)(out + (size_t)gmB * CDIM + gn) = vB;
            }
        }
    }
}

// ---------------------------------------------------------------------------
// Tensor-core flash attention (causal, tf32 mma.sync) — EXACT R6 (best: 443us).
// Block = 128 threads (4 warps), Q/K tiles 64; grid 2048, heavy-first.
// Q frags in registers; P transposed C-frag -> A-frag via shfl; 2 barriers/tile.
// ---------------------------------------------------------------------------
#define SA 68
#define ATTN_SMEM (2 * 64 * SA * 4)

__global__ __launch_bounds__(128) void attn_mma() {
    extern __shared__ uint32_t smw[];
    uint32_t* Ks = smw;               // 64 x SA (also Q staging pre-loop)
    uint32_t* Vt = smw + 64 * SA;     // 64 x SA  (Vt[d][key])

    const int t = threadIdx.x;
    const int lane = t & 31, w = t >> 5;
    const int qi = (gridDim.x - 1) - blockIdx.x;  // heavy tiles first
    const int bh = blockIdx.y;
    const int q0 = qi * 64;

    const float* Qg = g_Q + (size_t)bh * TLEN * HD;
    const float* Kg = g_K + (size_t)bh * TLEN * HD;
    const float* Vg = g_V + (size_t)bh * TLEN * HD;

    const int r0w = w * 16 + (lane >> 2);
    const int abase = r0w * SA;
    const int lk = lane & 3;
    const int src0 = (lane & 28) + ((lane >> 1) & 1);
    const int src1 = src0 + 2;
    const bool oddl = lane & 1;

    // Stage Q through the K buffer, then hoist fragments to registers.
    for (int i = t; i < 64 * 16; i += 128) {
        const int row = i >> 4, c4 = (i & 15) * 4;
        float4 v = *(const float4*)(Qg + (size_t)(q0 + row) * HD + c4);
        uint4 u;
        u.x = f2tf32(v.x * 0.125f);
        u.y = f2tf32(v.y * 0.125f);
        u.z = f2tf32(v.z * 0.125f);
        u.w = f2tf32(v.w * 0.125f);
        *(uint4*)&Ks[row * SA + c4] = u;
    }
    __syncthreads();
    uint32_t qf[8][4];
#pragma unroll
    for (int ks = 0; ks < 8; ks++) {
        const int kk = ks * 8 + lk;
        qf[ks][0] = Ks[abase + kk];
        qf[ks][1] = Ks[abase + 8 * SA + kk];
        qf[ks][2] = Ks[abase + kk + 4];
        qf[ks][3] = Ks[abase + 8 * SA + kk + 4];
    }

    float o[8][4];
#pragma unroll
    for (int j = 0; j < 8; j++)
#pragma unroll
        for (int e = 0; e < 4; e++) o[j][e] = 0.f;
    float m0 = -1e30f, m1 = -1e30f, l0 = 0.f, l1 = 0.f;

    for (int kt = 0; kt <= qi; kt++) {
        const int k0 = kt * 64;
        __syncthreads();  // Ks free of prior readers (incl. Q frag loads)
        for (int i = t; i < 64 * 16; i += 128) {
            const int row = i >> 4, c4 = (i & 15) * 4;
            float4 kv = *(const float4*)(Kg + (size_t)(k0 + row) * HD + c4);
            uint4 u;
            u.x = f2tf32(kv.x); u.y = f2tf32(kv.y);
            u.z = f2tf32(kv.z); u.w = f2tf32(kv.w);
            *(uint4*)&Ks[row * SA + c4] = u;
            float4 vv = *(const float4*)(Vg + (size_t)(k0 + row) * HD + c4);
            Vt[(c4 + 0) * SA + row] = f2tf32(vv.x);
            Vt[(c4 + 1) * SA + row] = f2tf32(vv.y);
            Vt[(c4 + 2) * SA + row] = f2tf32(vv.z);
            Vt[(c4 + 3) * SA + row] = f2tf32(vv.w);
        }
        __syncthreads();

        // S = (Q*scale) @ K^T   (Q from registers)
        float s[8][4];
#pragma unroll
        for (int j = 0; j < 8; j++)
#pragma unroll
            for (int e = 0; e < 4; e++) s[j][e] = 0.f;
#pragma unroll
        for (int ks = 0; ks < 8; ks++) {
            const int kk = ks * 8 + lk;
#pragma unroll
            for (int j = 0; j < 8; j++) {
                const int r = (j * 8 + (lane >> 2)) * SA;
                uint32_t b[2];
                b[0] = Ks[r + kk];
                b[1] = Ks[r + kk + 4];
                MMA_TF32(s[j], qf[ks], b);
            }
        }

        // Causal mask (diagonal tile only; uniform branch)
        if (kt == qi) {
            const int gr0 = q0 + r0w, gr1 = gr0 + 8;
#pragma unroll
            for (int j = 0; j < 8; j++) {
                const int c = k0 + j * 8 + 2 * lk;
                if (c > gr0) s[j][0] = -1e30f;
                if (c + 1 > gr0) s[j][1] = -1e30f;
                if (c > gr1) s[j][2] = -1e30f;
                if (c + 1 > gr1) s[j][3] = -1e30f;
            }
        }

        // Online softmax: rows r0w (c0,c1) and r0w+8 (c2,c3)
        float tm0 = -1e30f, tm1 = -1e30f;
#pragma unroll
        for (int j = 0; j < 8; j++) {
            tm0 = fmaxf(tm0, fmaxf(s[j][0], s[j][1]));
            tm1 = fmaxf(tm1, fmaxf(s[j][2], s[j][3]));
        }
        tm0 = fmaxf(tm0, __shfl_xor_sync(0xffffffffu, tm0, 1));
        tm0 = fmaxf(tm0, __shfl_xor_sync(0xffffffffu, tm0, 2));
        tm1 = fmaxf(tm1, __shfl_xor_sync(0xffffffffu, tm1, 1));
        tm1 = fmaxf(tm1, __shfl_xor_sync(0xffffffffu, tm1, 2));

        const float mn0 = fmaxf(m0, tm0), mn1 = fmaxf(m1, tm1);
        const float al0 = __expf(m0 - mn0), al1 = __expf(m1 - mn1);
        m0 = mn0; m1 = mn1;

        float rs0 = 0.f, rs1 = 0.f;
#pragma unroll
        for (int j = 0; j < 8; j++) {
            s[j][0] = __expf(s[j][0] - mn0); rs0 += s[j][0];
            s[j][1] = __expf(s[j][1] - mn0); rs0 += s[j][1];
            s[j][2] = __expf(s[j][2] - mn1); rs1 += s[j][2];
            s[j][3] = __expf(s[j][3] - mn1); rs1 += s[j][3];
        }
        rs0 += __shfl_xor_sync(0xffffffffu, rs0, 1);
        rs0 += __shfl_xor_sync(0xffffffffu, rs0, 2);
        rs1 += __shfl_xor_sync(0xffffffffu, rs1, 1);
        rs1 += __shfl_xor_sync(0xffffffffu, rs1, 2);
        l0 = l0 * al0 + rs0;
        l1 = l1 * al1 + rs1;
#pragma unroll
        for (int j = 0; j < 8; j++) {
            o[j][0] *= al0; o[j][1] *= al0;
            o[j][2] *= al1; o[j][3] *= al1;
        }

        // O += P @ V. P A-frags from s C-frags via in-register permute.
#pragma unroll
        for (int ks = 0; ks < 8; ks++) {
            float v00 = __shfl_sync(0xffffffffu, s[ks][0], src0);
            float v01 = __shfl_sync(0xffffffffu, s[ks][1], src0);
            float v20 = __shfl_sync(0xffffffffu, s[ks][2], src0);
            float v21 = __shfl_sync(0xffffffffu, s[ks][3], src0);
            float v0b = __shfl_sync(0xffffffffu, s[ks][0], src1);
            float v1b = __shfl_sync(0xffffffffu, s[ks][1], src1);
            float v2b = __shfl_sync(0xffffffffu, s[ks][2], src1);
            float v3b = __shfl_sync(0xffffffffu, s[ks][3], src1);
            uint32_t a[4];
            a[0] = f2tf32(oddl ? v01 : v00);
            a[1] = f2tf32(oddl ? v21 : v20);
            a[2] = f2tf32(oddl ? v1b : v0b);
            a[3] = f2tf32(oddl ? v3b : v2b);
            const int kk = ks * 8 + lk;
#pragma unroll
            for (int j = 0; j < 8; j++) {
                const int r = (j * 8 + (lane >> 2)) * SA;
                uint32_t b[2];
                b[0] = Vt[r + kk];
                b[1] = Vt[r + kk + 4];
                MMA_TF32(o[j], a, b);
            }
        }
    }

    // Epilogue -> g_att [B,T,C]
    const float inv0 = 1.f / l0, inv1 = 1.f / l1;
    const int b = bh >> 4, h = bh & 15;
    const int gr0 = q0 + r0w, gr1 = gr0 + 8;
    float* o0 = g_att + ((size_t)(b * TLEN + gr0)) * CDIM + h * HD;
    float* o1 = g_att + ((size_t)(b * TLEN + gr1)) * CDIM + h * HD;
#pragma unroll
    for (int j = 0; j < 8; j++) {
        const int c = j * 8 + 2 * lk;
        *(float2*)(o0 + c) = make_float2(o[j][0] * inv0, o[j][1] * inv0);
        *(float2*)(o1 + c) = make_float2(o[j][2] * inv1, o[j][3] * inv1);
    }
}

// ---------------------------------------------------------------------------
extern "C" void kernel_launch(void* const* d_in, const int* in_sizes, int n_in,
                              void* d_out, int out_size) {
    const float* x = (const float*)d_in[0];
    const float* W_qkv = (const float*)d_in[1];
    const float* b_qkv = (const float*)d_in[2];
    const float* W_proj = (const float*)d_in[3];
    const float* b_proj = (const float*)d_in[4];
    float* out = (float*)d_out;

    float *wqkvT = nullptr, *wprojT = nullptr, *attp = nullptr;
    cudaGetSymbolAddress((void**)&wqkvT, g_WqkvT);
    cudaGetSymbolAddress((void**)&wprojT, g_WprojT);
    cudaGetSymbolAddress((void**)&attp, g_att);

    cudaFuncSetAttribute(attn_mma, cudaFuncAttributeMaxDynamicSharedMemorySize,
                         ATTN_SMEM);
    cudaFuncSetAttribute(mm_tf32<0>, cudaFuncAttributeMaxDynamicSharedMemorySize,
                         MM_SMEM);
    cudaFuncSetAttribute(mm_tf32<1>, cudaFuncAttributeMaxDynamicSharedMemorySize,
                         MM_SMEM);

    transpose32<<<dim3(N3 / 32, CDIM / 32), 256>>>(W_qkv, wqkvT, CDIM, N3);
    transpose32<<<dim3(CDIM / 32, CDIM / 32), 256>>>(W_proj, wprojT, CDIM, CDIM);

    mm_tf32<0><<<dim3(N3 / 128, BT / 128), 256, MM_SMEM>>>(x, wqkvT, b_qkv, nullptr);

    attn_mma<<<dim3(TLEN / 64, BSZ * NH), 128, ATTN_SMEM>>>();

    mm_tf32<1><<<dim3(CDIM / 128, BT / 128), 256, MM_SMEM>>>(attp, wprojT, b_proj, out);
}

// round 10
// speedup vs baseline: 1.3401x; 1.0705x over previous
#include <cuda_runtime.h>
#include <cstdint>
#include <math.h>

#define BSZ 4
#define TLEN 2048
#define CDIM 1024
#define NH 16
#define HD 64
#define BT (BSZ * TLEN)      /* 8192 */
#define N3 (3 * CDIM)        /* 3072 */

// Scratch (allocation-free rule: __device__ globals)
__device__ float g_Q[BT * CDIM];      // [B,H,T,Dh]
__device__ float g_K[BT * CDIM];
__device__ float g_V[BT * CDIM];
__device__ float g_att[BT * CDIM];    // [B,T,C]
__device__ float g_WqkvT[N3 * CDIM];  // [3072,1024]  (W_qkv^T)
__device__ float g_WprojT[CDIM * CDIM];

// ---------------------------------------------------------------------------
// Portable tensor-core helpers (sm_80+ mma.sync — no 'a'-suffix features)
// ---------------------------------------------------------------------------
__device__ __forceinline__ uint32_t f2tf32(float x) {
    uint32_t u;
    asm("cvt.rna.tf32.f32 %0, %1;" : "=r"(u) : "f"(x));
    return u;
}

#define MMA_TF32(d, a, b)                                                        \
    asm volatile(                                                                \
        "mma.sync.aligned.m16n8k8.row.col.f32.tf32.tf32.f32 "                    \
        "{%0,%1,%2,%3}, {%4,%5,%6,%7}, {%8,%9}, {%0,%1,%2,%3};"                  \
        : "+f"((d)[0]), "+f"((d)[1]), "+f"((d)[2]), "+f"((d)[3])                 \
        : "r"((a)[0]), "r"((a)[1]), "r"((a)[2]), "r"((a)[3]),                    \
          "r"((b)[0]), "r"((b)[1]))

// ---------------------------------------------------------------------------
// One-shot weight transposes:  out[N,K] = in[K,N]^T
// ---------------------------------------------------------------------------
__global__ __launch_bounds__(256) void transpose32(const float* __restrict__ in,
                                                   float* __restrict__ out,
                                                   int R, int C) {
    __shared__ float tile[32][33];
    const int c0 = blockIdx.x * 32, r0 = blockIdx.y * 32;
    const int tx = threadIdx.x & 31, ty = threadIdx.x >> 5;
#pragma unroll
    for (int i = 0; i < 4; i++) {
        int r = ty + i * 8;
        tile[r][tx] = in[(size_t)(r0 + r) * C + c0 + tx];
    }
    __syncthreads();
#pragma unroll
    for (int i = 0; i < 4; i++) {
        int r = ty + i * 8;
        out[(size_t)(c0 + r) * R + r0 + tx] = tile[tx][r];
    }
}

// ---------------------------------------------------------------------------
// tf32 mma.sync GEMM, double-buffered smem, ONE barrier per K chunk (R9, best).
// MODE 0: QKV epilogue scatter -> g_Q/g_K/g_V;  MODE 1: plain out.
// ---------------------------------------------------------------------------
#define SSTR 36
#define MMT (128 * SSTR)
#define MM_SMEM (4 * MMT * 4)

template <int MODE>
__global__ __launch_bounds__(256, 2)
void mm_tf32(const float* __restrict__ A, const float* __restrict__ Bt,
             const float* __restrict__ bias, float* __restrict__ out) {
    extern __shared__ uint32_t gsm[];   // [A0 | B0 | A1 | B1]

    const int t = threadIdx.x;
    const int m0 = blockIdx.y * 128;
    const int n0 = blockIdx.x * 128;
    const int lane = t & 31, w = t >> 5;
    const int wr = w >> 2, wc = w & 3;

    float d[4][4][4];
#pragma unroll
    for (int i = 0; i < 4; i++)
#pragma unroll
        for (int j = 0; j < 4; j++)
#pragma unroll
            for (int e = 0; e < 4; e++) d[i][j][e] = 0.f;

    const int gr = t >> 3;
    const int gc4 = (t & 7) * 4;
    const float* Ap = A + (size_t)(m0 + gr) * CDIM + gc4;
    const float* Bp = Bt + (size_t)(n0 + gr) * CDIM + gc4;

    const int ar = wr * 64 + (lane >> 2);
    const int ac = lane & 3;
    const int br = wc * 32 + (lane >> 2);

    for (int k0 = 0; k0 < CDIM; k0 += 32) {
        const int st = (k0 >> 5) & 1;
        uint32_t* As = gsm + st * 2 * MMT;
        uint32_t* Bs = As + MMT;

#pragma unroll
        for (int p = 0; p < 4; p++) {
            const int row = gr + p * 32;
            float4 va = *(const float4*)(Ap + (size_t)(p * 32) * CDIM + k0);
            float4 vb = *(const float4*)(Bp + (size_t)(p * 32) * CDIM + k0);
            uint32_t* ad = &As[row * SSTR + gc4];
            uint32_t* bd = &Bs[row * SSTR + gc4];
            ad[0] = f2tf32(va.x); ad[1] = f2tf32(va.y);
            ad[2] = f2tf32(va.z); ad[3] = f2tf32(va.w);
            bd[0] = f2tf32(vb.x); bd[1] = f2tf32(vb.y);
            bd[2] = f2tf32(vb.z); bd[3] = f2tf32(vb.w);
        }
        __syncthreads();

#pragma unroll
        for (int ks = 0; ks < 4; ks++) {
            const int kk = ks * 8 + ac;
            uint32_t a[4][4], b[4][2];
#pragma unroll
            for (int i = 0; i < 4; i++) {
                const int r = (ar + i * 16) * SSTR;
                a[i][0] = As[r + kk];
                a[i][1] = As[r + 8 * SSTR + kk];
                a[i][2] = As[r + kk + 4];
                a[i][3] = As[r + 8 * SSTR + kk + 4];
            }
#pragma unroll
            for (int j = 0; j < 4; j++) {
                const int r = (br + j * 8) * SSTR;
                b[j][0] = Bs[r + kk];
                b[j][1] = Bs[r + kk + 4];
            }
#pragma unroll
            for (int i = 0; i < 4; i++)
#pragma unroll
                for (int j = 0; j < 4; j++) MMA_TF32(d[i][j], a[i], b[j]);
        }
    }

    const int r0 = lane >> 2, c0 = (lane & 3) * 2;
#pragma unroll
    for (int i = 0; i < 4; i++) {
        const int gmA = m0 + wr * 64 + i * 16 + r0;
        const int gmB = gmA + 8;
#pragma unroll
        for (int j = 0; j < 4; j++) {
            const int gn = n0 + wc * 32 + j * 8 + c0;
            const float bx = bias[gn], by = bias[gn + 1];
            float2 vA = make_float2(d[i][j][0] + bx, d[i][j][1] + by);
            float2 vB = make_float2(d[i][j][2] + bx, d[i][j][3] + by);
            if (MODE == 0) {
                const int which = gn >> 10;
                const int c = gn & 1023;
                const int h = c >> 6, d0 = c & 63;
                float* base = (which == 0) ? g_Q : ((which == 1) ? g_K : g_V);
                const int bA = gmA >> 11, tA = gmA & 2047;
                const int bB = gmB >> 11, tB = gmB & 2047;
                *(float2*)(base + ((size_t)(bA * NH + h) * TLEN + tA) * HD + d0) = vA;
                *(float2*)(base + ((size_t)(bB * NH + h) * TLEN + tB) * HD + d0) = vB;
            } else {
                *(float2*)(out + (size_t)gmA * CDIM + gn) = vA;
                *(float2*)(out + (size_t)gmB * CDIM + gn) = vB;
            }
        }
    }
}

// ---------------------------------------------------------------------------
// Tensor-core flash attention v6 (causal, tf32 mma.sync).
// Block = 128 threads (4 warps), Q/K tiles 64; grid 2048, heavy-first.
// CHANGE vs R9: V stored ROW-MAJOR Vs[key][d] (stride 68) -> staging stores
// conflict-free STS.128 (was 16-way conflicted scatter); PV B-frag loads read
// Vs[key][d] at <=2-way conflict. Q frags in registers; P via shfl transpose.
// ---------------------------------------------------------------------------
#define SA 68
#define ATTN_SMEM (2 * 64 * SA * 4)

__global__ __launch_bounds__(128) void attn_mma() {
    extern __shared__ uint32_t smw[];
    uint32_t* Ks = smw;               // 64 x SA (also Q staging pre-loop)
    uint32_t* Vs = smw + 64 * SA;     // 64 x SA  (Vs[key][d], row-major)

    const int t = threadIdx.x;
    const int lane = t & 31, w = t >> 5;
    const int qi = (gridDim.x - 1) - blockIdx.x;  // heavy tiles first
    const int bh = blockIdx.y;
    const int q0 = qi * 64;

    const float* Qg = g_Q + (size_t)bh * TLEN * HD;
    const float* Kg = g_K + (size_t)bh * TLEN * HD;
    const float* Vg = g_V + (size_t)bh * TLEN * HD;

    const int r0w = w * 16 + (lane >> 2);
    const int abase = r0w * SA;
    const int lk = lane & 3;
    const int src0 = (lane & 28) + ((lane >> 1) & 1);
    const int src1 = src0 + 2;
    const bool oddl = lane & 1;

    // Stage Q through the K buffer, then hoist fragments to registers.
    for (int i = t; i < 64 * 16; i += 128) {
        const int row = i >> 4, c4 = (i & 15) * 4;
        float4 v = *(const float4*)(Qg + (size_t)(q0 + row) * HD + c4);
        uint4 u;
        u.x = f2tf32(v.x * 0.125f);
        u.y = f2tf32(v.y * 0.125f);
        u.z = f2tf32(v.z * 0.125f);
        u.w = f2tf32(v.w * 0.125f);
        *(uint4*)&Ks[row * SA + c4] = u;
    }
    __syncthreads();
    uint32_t qf[8][4];
#pragma unroll
    for (int ks = 0; ks < 8; ks++) {
        const int kk = ks * 8 + lk;
        qf[ks][0] = Ks[abase + kk];
        qf[ks][1] = Ks[abase + 8 * SA + kk];
        qf[ks][2] = Ks[abase + kk + 4];
        qf[ks][3] = Ks[abase + 8 * SA + kk + 4];
    }

    float o[8][4];
#pragma unroll
    for (int j = 0; j < 8; j++)
#pragma unroll
        for (int e = 0; e < 4; e++) o[j][e] = 0.f;
    float m0 = -1e30f, m1 = -1e30f, l0 = 0.f, l1 = 0.f;

    for (int kt = 0; kt <= qi; kt++) {
        const int k0 = kt * 64;
        __syncthreads();  // Ks/Vs free of prior readers (incl. Q frag loads)
        for (int i = t; i < 64 * 16; i += 128) {
            const int row = i >> 4, c4 = (i & 15) * 4;
            float4 kv = *(const float4*)(Kg + (size_t)(k0 + row) * HD + c4);
            uint4 u;
            u.x = f2tf32(kv.x); u.y = f2tf32(kv.y);
            u.z = f2tf32(kv.z); u.w = f2tf32(kv.w);
            *(uint4*)&Ks[row * SA + c4] = u;
            float4 vv = *(const float4*)(Vg + (size_t)(k0 + row) * HD + c4);
            uint4 uv;
            uv.x = f2tf32(vv.x); uv.y = f2tf32(vv.y);
            uv.z = f2tf32(vv.z); uv.w = f2tf32(vv.w);
            *(uint4*)&Vs[row * SA + c4] = uv;
        }
        __syncthreads();

        // S = (Q*scale) @ K^T   (Q from registers)
        float s[8][4];
#pragma unroll
        for (int j = 0; j < 8; j++)
#pragma unroll
            for (int e = 0; e < 4; e++) s[j][e] = 0.f;
#pragma unroll
        for (int ks = 0; ks < 8; ks++) {
            const int kk = ks * 8 + lk;
#pragma unroll
            for (int j = 0; j < 8; j++) {
                const int r = (j * 8 + (lane >> 2)) * SA;
                uint32_t b[2];
                b[0] = Ks[r + kk];
                b[1] = Ks[r + kk + 4];
                MMA_TF32(s[j], qf[ks], b);
            }
        }

        // Causal mask (diagonal tile only; uniform branch)
        if (kt == qi) {
            const int gr0 = q0 + r0w, gr1 = gr0 + 8;
#pragma unroll
            for (int j = 0; j < 8; j++) {
                const int c = k0 + j * 8 + 2 * lk;
                if (c > gr0) s[j][0] = -1e30f;
                if (c + 1 > gr0) s[j][1] = -1e30f;
                if (c > gr1) s[j][2] = -1e30f;
                if (c + 1 > gr1) s[j][3] = -1e30f;
            }
        }

        // Online softmax: rows r0w (c0,c1) and r0w+8 (c2,c3)
        float tm0 = -1e30f, tm1 = -1e30f;
#pragma unroll
        for (int j = 0; j < 8; j++) {
            tm0 = fmaxf(tm0, fmaxf(s[j][0], s[j][1]));
            tm1 = fmaxf(tm1, fmaxf(s[j][2], s[j][3]));
        }
        tm0 = fmaxf(tm0, __shfl_xor_sync(0xffffffffu, tm0, 1));
        tm0 = fmaxf(tm0, __shfl_xor_sync(0xffffffffu, tm0, 2));
        tm1 = fmaxf(tm1, __shfl_xor_sync(0xffffffffu, tm1, 1));
        tm1 = fmaxf(tm1, __shfl_xor_sync(0xffffffffu, tm1, 2));

        const float mn0 = fmaxf(m0, tm0), mn1 = fmaxf(m1, tm1);
        const float al0 = __expf(m0 - mn0), al1 = __expf(m1 - mn1);
        m0 = mn0; m1 = mn1;

        float rs0 = 0.f, rs1 = 0.f;
#pragma unroll
        for (int j = 0; j < 8; j++) {
            s[j][0] = __expf(s[j][0] - mn0); rs0 += s[j][0];
            s[j][1] = __expf(s[j][1] - mn0); rs0 += s[j][1];
            s[j][2] = __expf(s[j][2] - mn1); rs1 += s[j][2];
            s[j][3] = __expf(s[j][3] - mn1); rs1 += s[j][3];
        }
        rs0 += __shfl_xor_sync(0xffffffffu, rs0, 1);
        rs0 += __shfl_xor_sync(0xffffffffu, rs0, 2);
        rs1 += __shfl_xor_sync(0xffffffffu, rs1, 1);
        rs1 += __shfl_xor_sync(0xffffffffu, rs1, 2);
        l0 = l0 * al0 + rs0;
        l1 = l1 * al1 + rs1;
#pragma unroll
        for (int j = 0; j < 8; j++) {
            o[j][0] *= al0; o[j][1] *= al0;
            o[j][2] *= al1; o[j][3] *= al1;
        }

        // O += P @ V. P A-frags from s C-frags via in-register permute.
        // B-frags from row-major Vs: B(k=key, n=d), key = ks*8+lk (+4).
#pragma unroll
        for (int ks = 0; ks < 8; ks++) {
            float v00 = __shfl_sync(0xffffffffu, s[ks][0], src0);
            float v01 = __shfl_sync(0xffffffffu, s[ks][1], src0);
            float v20 = __shfl_sync(0xffffffffu, s[ks][2], src0);
            float v21 = __shfl_sync(0xffffffffu, s[ks][3], src0);
            float v0b = __shfl_sync(0xffffffffu, s[ks][0], src1);
            float v1b = __shfl_sync(0xffffffffu, s[ks][1], src1);
            float v2b = __shfl_sync(0xffffffffu, s[ks][2], src1);
            float v3b = __shfl_sync(0xffffffffu, s[ks][3], src1);
            uint32_t a[4];
            a[0] = f2tf32(oddl ? v01 : v00);
            a[1] = f2tf32(oddl ? v21 : v20);
            a[2] = f2tf32(oddl ? v1b : v0b);
            a[3] = f2tf32(oddl ? v3b : v2b);
            const int vr0 = (ks * 8 + lk) * SA;
            const int vr1 = (ks * 8 + lk + 4) * SA;
#pragma unroll
            for (int j = 0; j < 8; j++) {
                const int dcol = j * 8 + (lane >> 2);
                uint32_t b[2];
                b[0] = Vs[vr0 + dcol];
                b[1] = Vs[vr1 + dcol];
                MMA_TF32(o[j], a, b);
            }
        }
    }

    // Epilogue -> g_att [B,T,C]
    const float inv0 = 1.f / l0, inv1 = 1.f / l1;
    const int b = bh >> 4, h = bh & 15;
    const int gr0 = q0 + r0w, gr1 = gr0 + 8;
    float* o0 = g_att + ((size_t)(b * TLEN + gr0)) * CDIM + h * HD;
    float* o1 = g_att + ((size_t)(b * TLEN + gr1)) * CDIM + h * HD;
#pragma unroll
    for (int j = 0; j < 8; j++) {
        const int c = j * 8 + 2 * lk;
        *(float2*)(o0 + c) = make_float2(o[j][0] * inv0, o[j][1] * inv0);
        *(float2*)(o1 + c) = make_float2(o[j][2] * inv1, o[j][3] * inv1);
    }
}

// ---------------------------------------------------------------------------
extern "C" void kernel_launch(void* const* d_in, const int* in_sizes, int n_in,
                              void* d_out, int out_size) {
    const float* x = (const float*)d_in[0];
    const float* W_qkv = (const float*)d_in[1];
    const float* b_qkv = (const float*)d_in[2];
    const float* W_proj = (const float*)d_in[3];
    const float* b_proj = (const float*)d_in[4];
    float* out = (float*)d_out;

    float *wqkvT = nullptr, *wprojT = nullptr, *attp = nullptr;
    cudaGetSymbolAddress((void**)&wqkvT, g_WqkvT);
    cudaGetSymbolAddress((void**)&wprojT, g_WprojT);
    cudaGetSymbolAddress((void**)&attp, g_att);

    cudaFuncSetAttribute(attn_mma, cudaFuncAttributeMaxDynamicSharedMemorySize,
                         ATTN_SMEM);
    cudaFuncSetAttribute(mm_tf32<0>, cudaFuncAttributeMaxDynamicSharedMemorySize,
                         MM_SMEM);
    cudaFuncSetAttribute(mm_tf32<1>, cudaFuncAttributeMaxDynamicSharedMemorySize,
                         MM_SMEM);

    transpose32<<<dim3(N3 / 32, CDIM / 32), 256>>>(W_qkv, wqkvT, CDIM, N3);
    transpose32<<<dim3(CDIM / 32, CDIM / 32), 256>>>(W_proj, wprojT, CDIM, CDIM);

    mm_tf32<0><<<dim3(N3 / 128, BT / 128), 256, MM_SMEM>>>(x, wqkvT, b_qkv, nullptr);

    attn_mma<<<dim3(TLEN / 64, BSZ * NH), 128, ATTN_SMEM>>>();

    mm_tf32<1><<<dim3(CDIM / 128, BT / 128), 256, MM_SMEM>>>(attp, wprojT, b_proj, out);
}

// round 11
// speedup vs baseline: 1.3479x; 1.0058x over previous
#include <cuda_runtime.h>
#include <cstdint>
#include <math.h>

#define BSZ 4
#define TLEN 2048
#define CDIM 1024
#define NH 16
#define HD 64
#define BT (BSZ * TLEN)      /* 8192 */
#define N3 (3 * CDIM)        /* 3072 */

// Scratch (allocation-free rule: __device__ globals)
__device__ float g_Q[BT * CDIM];      // [B,H,T,Dh]
__device__ float g_K[BT * CDIM];
__device__ float g_V[BT * CDIM];
__device__ float g_att[BT * CDIM];    // [B,T,C] (tf32-rounded bits)
__device__ float g_WqkvT[N3 * CDIM];  // [3072,1024]  (W_qkv^T, tf32-rounded)
__device__ float g_WprojT[CDIM * CDIM]; // (W_proj^T, tf32-rounded)

// ---------------------------------------------------------------------------
// Portable tensor-core helpers (sm_80+ mma.sync — no 'a'-suffix features)
// ---------------------------------------------------------------------------
__device__ __forceinline__ uint32_t f2tf32(float x) {
    uint32_t u;
    asm("cvt.rna.tf32.f32 %0, %1;" : "=r"(u) : "f"(x));
    return u;
}

#define MMA_TF32(d, a, b)                                                        \
    asm volatile(                                                                \
        "mma.sync.aligned.m16n8k8.row.col.f32.tf32.tf32.f32 "                    \
        "{%0,%1,%2,%3}, {%4,%5,%6,%7}, {%8,%9}, {%0,%1,%2,%3};"                  \
        : "+f"((d)[0]), "+f"((d)[1]), "+f"((d)[2]), "+f"((d)[3])                 \
        : "r"((a)[0]), "r"((a)[1]), "r"((a)[2]), "r"((a)[3]),                    \
          "r"((b)[0]), "r"((b)[1]))

// ---------------------------------------------------------------------------
// One-shot weight transposes + tf32 pre-round: out[N,K] = rna(in[K,N]^T).
// GEMM B-side cvt becomes redundant (rna is idempotent) and is skipped.
// ---------------------------------------------------------------------------
__global__ __launch_bounds__(256) void transpose32(const float* __restrict__ in,
                                                   float* __restrict__ out,
                                                   int R, int C) {
    __shared__ float tile[32][33];
    const int c0 = blockIdx.x * 32, r0 = blockIdx.y * 32;
    const int tx = threadIdx.x & 31, ty = threadIdx.x >> 5;
#pragma unroll
    for (int i = 0; i < 4; i++) {
        int r = ty + i * 8;
        tile[r][tx] = in[(size_t)(r0 + r) * C + c0 + tx];
    }
    __syncthreads();
#pragma unroll
    for (int i = 0; i < 4; i++) {
        int r = ty + i * 8;
        out[(size_t)(c0 + r) * R + r0 + tx] =
            __uint_as_float(f2tf32(tile[tx][r]));
    }
}

// ---------------------------------------------------------------------------
// tf32 mma.sync GEMM, double-buffered smem, ONE barrier per K chunk.
// Staging: LDG.128 -> (cvt A if CVT_A) -> STS.128 (conflict-free phases).
// B operand arrives pre-rounded (transpose32 / attn epilogue) -> no cvt.
// MODE 0: QKV epilogue scatter -> g_Q/g_K/g_V;  MODE 1: plain out.
// ---------------------------------------------------------------------------
#define SSTR 36
#define MMT (128 * SSTR)
#define MM_SMEM (4 * MMT * 4)

template <int MODE, bool CVT_A>
__global__ __launch_bounds__(256, 2)
void mm_tf32(const float* __restrict__ A, const float* __restrict__ Bt,
             const float* __restrict__ bias, float* __restrict__ out) {
    extern __shared__ uint32_t gsm[];   // [A0 | B0 | A1 | B1]

    const int t = threadIdx.x;
    const int m0 = blockIdx.y * 128;
    const int n0 = blockIdx.x * 128;
    const int lane = t & 31, w = t >> 5;
    const int wr = w >> 2, wc = w & 3;

    float d[4][4][4];
#pragma unroll
    for (int i = 0; i < 4; i++)
#pragma unroll
        for (int j = 0; j < 4; j++)
#pragma unroll
            for (int e = 0; e < 4; e++) d[i][j][e] = 0.f;

    const int gr = t >> 3;
    const int gc4 = (t & 7) * 4;
    const float* Ap = A + (size_t)(m0 + gr) * CDIM + gc4;
    const float* Bp = Bt + (size_t)(n0 + gr) * CDIM + gc4;

    const int ar = wr * 64 + (lane >> 2);
    const int ac = lane & 3;
    const int br = wc * 32 + (lane >> 2);

    for (int k0 = 0; k0 < CDIM; k0 += 32) {
        const int st = (k0 >> 5) & 1;
        uint32_t* As = gsm + st * 2 * MMT;
        uint32_t* Bs = As + MMT;

#pragma unroll
        for (int p = 0; p < 4; p++) {
            const int row = gr + p * 32;
            float4 va = *(const float4*)(Ap + (size_t)(p * 32) * CDIM + k0);
            float4 vb = *(const float4*)(Bp + (size_t)(p * 32) * CDIM + k0);
            uint4 ua;
            if (CVT_A) {
                ua.x = f2tf32(va.x); ua.y = f2tf32(va.y);
                ua.z = f2tf32(va.z); ua.w = f2tf32(va.w);
            } else {
                ua.x = __float_as_uint(va.x); ua.y = __float_as_uint(va.y);
                ua.z = __float_as_uint(va.z); ua.w = __float_as_uint(va.w);
            }
            uint4 ub;  // pre-rounded
            ub.x = __float_as_uint(vb.x); ub.y = __float_as_uint(vb.y);
            ub.z = __float_as_uint(vb.z); ub.w = __float_as_uint(vb.w);
            *(uint4*)&As[row * SSTR + gc4] = ua;
            *(uint4*)&Bs[row * SSTR + gc4] = ub;
        }
        __syncthreads();

#pragma unroll
        for (int ks = 0; ks < 4; ks++) {
            const int kk = ks * 8 + ac;
            uint32_t a[4][4], b[4][2];
#pragma unroll
            for (int i = 0; i < 4; i++) {
                const int r = (ar + i * 16) * SSTR;
                a[i][0] = As[r + kk];
                a[i][1] = As[r + 8 * SSTR + kk];
                a[i][2] = As[r + kk + 4];
                a[i][3] = As[r + 8 * SSTR + kk + 4];
            }
#pragma unroll
            for (int j = 0; j < 4; j++) {
                const int r = (br + j * 8) * SSTR;
                b[j][0] = Bs[r + kk];
                b[j][1] = Bs[r + kk + 4];
            }
#pragma unroll
            for (int i = 0; i < 4; i++)
#pragma unroll
                for (int j = 0; j < 4; j++) MMA_TF32(d[i][j], a[i], b[j]);
        }
    }

    const int r0 = lane >> 2, c0 = (lane & 3) * 2;
#pragma unroll
    for (int i = 0; i < 4; i++) {
        const int gmA = m0 + wr * 64 + i * 16 + r0;
        const int gmB = gmA + 8;
#pragma unroll
        for (int j = 0; j < 4; j++) {
            const int gn = n0 + wc * 32 + j * 8 + c0;
            const float bx = bias[gn], by = bias[gn + 1];
            float2 vA = make_float2(d[i][j][0] + bx, d[i][j][1] + by);
            float2 vB = make_float2(d[i][j][2] + bx, d[i][j][3] + by);
            if (MODE == 0) {
                const int which = gn >> 10;
                const int c = gn & 1023;
                const int h = c >> 6, d0 = c & 63;
                float* base = (which == 0) ? g_Q : ((which == 1) ? g_K : g_V);
                const int bA = gmA >> 11, tA = gmA & 2047;
                const int bB = gmB >> 11, tB = gmB & 2047;
                *(float2*)(base + ((size_t)(bA * NH + h) * TLEN + tA) * HD + d0) = vA;
                *(float2*)(base + ((size_t)(bB * NH + h) * TLEN + tB) * HD + d0) = vB;
            } else {
                *(float2*)(out + (size_t)gmA * CDIM + gn) = vA;
                *(float2*)(out + (size_t)gmB * CDIM + gn) = vB;
            }
        }
    }
}

// ---------------------------------------------------------------------------
// Tensor-core flash attention v6 (causal, tf32 mma.sync) — R10 (365us), with
// tf32 pre-round in the epilogue so proj skips its A-side cvt (bit-exact).
// ---------------------------------------------------------------------------
#define SA 68
#define ATTN_SMEM (2 * 64 * SA * 4)

__global__ __launch_bounds__(128) void attn_mma() {
    extern __shared__ uint32_t smw[];
    uint32_t* Ks = smw;               // 64 x SA (also Q staging pre-loop)
    uint32_t* Vs = smw + 64 * SA;     // 64 x SA  (Vs[key][d], row-major)

    const int t = threadIdx.x;
    const int lane = t & 31, w = t >> 5;
    const int qi = (gridDim.x - 1) - blockIdx.x;  // heavy tiles first
    const int bh = blockIdx.y;
    const int q0 = qi * 64;

    const float* Qg = g_Q + (size_t)bh * TLEN * HD;
    const float* Kg = g_K + (size_t)bh * TLEN * HD;
    const float* Vg = g_V + (size_t)bh * TLEN * HD;

    const int r0w = w * 16 + (lane >> 2);
    const int abase = r0w * SA;
    const int lk = lane & 3;
    const int src0 = (lane & 28) + ((lane >> 1) & 1);
    const int src1 = src0 + 2;
    const bool oddl = lane & 1;

    // Stage Q through the K buffer, then hoist fragments to registers.
    for (int i = t; i < 64 * 16; i += 128) {
        const int row = i >> 4, c4 = (i & 15) * 4;
        float4 v = *(const float4*)(Qg + (size_t)(q0 + row) * HD + c4);
        uint4 u;
        u.x = f2tf32(v.x * 0.125f);
        u.y = f2tf32(v.y * 0.125f);
        u.z = f2tf32(v.z * 0.125f);
        u.w = f2tf32(v.w * 0.125f);
        *(uint4*)&Ks[row * SA + c4] = u;
    }
    __syncthreads();
    uint32_t qf[8][4];
#pragma unroll
    for (int ks = 0; ks < 8; ks++) {
        const int kk = ks * 8 + lk;
        qf[ks][0] = Ks[abase + kk];
        qf[ks][1] = Ks[abase + 8 * SA + kk];
        qf[ks][2] = Ks[abase + kk + 4];
        qf[ks][3] = Ks[abase + 8 * SA + kk + 4];
    }

    float o[8][4];
#pragma unroll
    for (int j = 0; j < 8; j++)
#pragma unroll
        for (int e = 0; e < 4; e++) o[j][e] = 0.f;
    float m0 = -1e30f, m1 = -1e30f, l0 = 0.f, l1 = 0.f;

    for (int kt = 0; kt <= qi; kt++) {
        const int k0 = kt * 64;
        __syncthreads();  // Ks/Vs free of prior readers (incl. Q frag loads)
        for (int i = t; i < 64 * 16; i += 128) {
            const int row = i >> 4, c4 = (i & 15) * 4;
            float4 kv = *(const float4*)(Kg + (size_t)(k0 + row) * HD + c4);
            uint4 u;
            u.x = f2tf32(kv.x); u.y = f2tf32(kv.y);
            u.z = f2tf32(kv.z); u.w = f2tf32(kv.w);
            *(uint4*)&Ks[row * SA + c4] = u;
            float4 vv = *(const float4*)(Vg + (size_t)(k0 + row) * HD + c4);
            uint4 uv;
            uv.x = f2tf32(vv.x); uv.y = f2tf32(vv.y);
            uv.z = f2tf32(vv.z); uv.w = f2tf32(vv.w);
            *(uint4*)&Vs[row * SA + c4] = uv;
        }
        __syncthreads();

        // S = (Q*scale) @ K^T   (Q from registers)
        float s[8][4];
#pragma unroll
        for (int j = 0; j < 8; j++)
#pragma unroll
            for (int e = 0; e < 4; e++) s[j][e] = 0.f;
#pragma unroll
        for (int ks = 0; ks < 8; ks++) {
            const int kk = ks * 8 + lk;
#pragma unroll
            for (int j = 0; j < 8; j++) {
                const int r = (j * 8 + (lane >> 2)) * SA;
                uint32_t b[2];
                b[0] = Ks[r + kk];
                b[1] = Ks[r + kk + 4];
                MMA_TF32(s[j], qf[ks], b);
            }
        }

        // Causal mask (diagonal tile only; uniform branch)
        if (kt == qi) {
            const int gr0 = q0 + r0w, gr1 = gr0 + 8;
#pragma unroll
            for (int j = 0; j < 8; j++) {
                const int c = k0 + j * 8 + 2 * lk;
                if (c > gr0) s[j][0] = -1e30f;
                if (c + 1 > gr0) s[j][1] = -1e30f;
                if (c > gr1) s[j][2] = -1e30f;
                if (c + 1 > gr1) s[j][3] = -1e30f;
            }
        }

        // Online softmax: rows r0w (c0,c1) and r0w+8 (c2,c3)
        float tm0 = -1e30f, tm1 = -1e30f;
#pragma unroll
        for (int j = 0; j < 8; j++) {
            tm0 = fmaxf(tm0, fmaxf(s[j][0], s[j][1]));
            tm1 = fmaxf(tm1, fmaxf(s[j][2], s[j][3]));
        }
        tm0 = fmaxf(tm0, __shfl_xor_sync(0xffffffffu, tm0, 1));
        tm0 = fmaxf(tm0, __shfl_xor_sync(0xffffffffu, tm0, 2));
        tm1 = fmaxf(tm1, __shfl_xor_sync(0xffffffffu, tm1, 1));
        tm1 = fmaxf(tm1, __shfl_xor_sync(0xffffffffu, tm1, 2));

        const float mn0 = fmaxf(m0, tm0), mn1 = fmaxf(m1, tm1);
        const float al0 = __expf(m0 - mn0), al1 = __expf(m1 - mn1);
        m0 = mn0; m1 = mn1;

        float rs0 = 0.f, rs1 = 0.f;
#pragma unroll
        for (int j = 0; j < 8; j++) {
            s[j][0] = __expf(s[j][0] - mn0); rs0 += s[j][0];
            s[j][1] = __expf(s[j][1] - mn0); rs0 += s[j][1];
            s[j][2] = __expf(s[j][2] - mn1); rs1 += s[j][2];
            s[j][3] = __expf(s[j][3] - mn1); rs1 += s[j][3];
        }
        rs0 += __shfl_xor_sync(0xffffffffu, rs0, 1);
        rs0 += __shfl_xor_sync(0xffffffffu, rs0, 2);
        rs1 += __shfl_xor_sync(0xffffffffu, rs1, 1);
        rs1 += __shfl_xor_sync(0xffffffffu, rs1, 2);
        l0 = l0 * al0 + rs0;
        l1 = l1 * al1 + rs1;
#pragma unroll
        for (int j = 0; j < 8; j++) {
            o[j][0] *= al0; o[j][1] *= al0;
            o[j][2] *= al1; o[j][3] *= al1;
        }

        // O += P @ V. P A-frags from s C-frags via in-register permute.
#pragma unroll
        for (int ks = 0; ks < 8; ks++) {
            float v00 = __shfl_sync(0xffffffffu, s[ks][0], src0);
            float v01 = __shfl_sync(0xffffffffu, s[ks][1], src0);
            float v20 = __shfl_sync(0xffffffffu, s[ks][2], src0);
            float v21 = __shfl_sync(0xffffffffu, s[ks][3], src0);
            float v0b = __shfl_sync(0xffffffffu, s[ks][0], src1);
            float v1b = __shfl_sync(0xffffffffu, s[ks][1], src1);
            float v2b = __shfl_sync(0xffffffffu, s[ks][2], src1);
            float v3b = __shfl_sync(0xffffffffu, s[ks][3], src1);
            uint32_t a[4];
            a[0] = f2tf32(oddl ? v01 : v00);
            a[1] = f2tf32(oddl ? v21 : v20);
            a[2] = f2tf32(oddl ? v1b : v0b);
            a[3] = f2tf32(oddl ? v3b : v2b);
            const int vr0 = (ks * 8 + lk) * SA;
            const int vr1 = (ks * 8 + lk + 4) * SA;
#pragma unroll
            for (int j = 0; j < 8; j++) {
                const int dcol = j * 8 + (lane >> 2);
                uint32_t b[2];
                b[0] = Vs[vr0 + dcol];
                b[1] = Vs[vr1 + dcol];
                MMA_TF32(o[j], a, b);
            }
        }
    }

    // Epilogue -> g_att [B,T,C], tf32 pre-rounded (proj skips its A cvt)
    const float inv0 = 1.f / l0, inv1 = 1.f / l1;
    const int b = bh >> 4, h = bh & 15;
    const int gr0 = q0 + r0w, gr1 = gr0 + 8;
    float* o0 = g_att + ((size_t)(b * TLEN + gr0)) * CDIM + h * HD;
    float* o1 = g_att + ((size_t)(b * TLEN + gr1)) * CDIM + h * HD;
#pragma unroll
    for (int j = 0; j < 8; j++) {
        const int c = j * 8 + 2 * lk;
        *(float2*)(o0 + c) = make_float2(__uint_as_float(f2tf32(o[j][0] * inv0)),
                                         __uint_as_float(f2tf32(o[j][1] * inv0)));
        *(float2*)(o1 + c) = make_float2(__uint_as_float(f2tf32(o[j][2] * inv1)),
                                         __uint_as_float(f2tf32(o[j][3] * inv1)));
    }
}

// ---------------------------------------------------------------------------
extern "C" void kernel_launch(void* const* d_in, const int* in_sizes, int n_in,
                              void* d_out, int out_size) {
    const float* x = (const float*)d_in[0];
    const float* W_qkv = (const float*)d_in[1];
    const float* b_qkv = (const float*)d_in[2];
    const float* W_proj = (const float*)d_in[3];
    const float* b_proj = (const float*)d_in[4];
    float* out = (float*)d_out;

    float *wqkvT = nullptr, *wprojT = nullptr, *attp = nullptr;
    cudaGetSymbolAddress((void**)&wqkvT, g_WqkvT);
    cudaGetSymbolAddress((void**)&wprojT, g_WprojT);
    cudaGetSymbolAddress((void**)&attp, g_att);

    cudaFuncSetAttribute(attn_mma, cudaFuncAttributeMaxDynamicSharedMemorySize,
                         ATTN_SMEM);
    cudaFuncSetAttribute(mm_tf32<0, true>,
                         cudaFuncAttributeMaxDynamicSharedMemorySize, MM_SMEM);
    cudaFuncSetAttribute(mm_tf32<1, false>,
                         cudaFuncAttributeMaxDynamicSharedMemorySize, MM_SMEM);

    transpose32<<<dim3(N3 / 32, CDIM / 32), 256>>>(W_qkv, wqkvT, CDIM, N3);
    transpose32<<<dim3(CDIM / 32, CDIM / 32), 256>>>(W_proj, wprojT, CDIM, CDIM);

    mm_tf32<0, true><<<dim3(N3 / 128, BT / 128), 256, MM_SMEM>>>(
        x, wqkvT, b_qkv, nullptr);

    attn_mma<<<dim3(TLEN / 64, BSZ * NH), 128, ATTN_SMEM>>>();

    mm_tf32<1, false><<<dim3(CDIM / 128, BT / 128), 256, MM_SMEM>>>(
        attp, wprojT, b_proj, out);
}

// round 12
// speedup vs baseline: 1.3818x; 1.0251x over previous
#include <cuda_runtime.h>
#include <cstdint>
#include <math.h>

#define BSZ 4
#define TLEN 2048
#define CDIM 1024
#define NH 16
#define HD 64
#define BT (BSZ * TLEN)      /* 8192 */
#define N3 (3 * CDIM)        /* 3072 */

// Scratch (allocation-free rule: __device__ globals)
__device__ float g_Q[BT * CDIM];      // [B,H,T,Dh]
__device__ float g_K[BT * CDIM];
__device__ float g_V[BT * CDIM];
__device__ float g_att[BT * CDIM];    // [B,T,C] (tf32-rounded bits)
__device__ float g_WqkvT[N3 * CDIM];  // [3072,1024]  (W_qkv^T, tf32-rounded)
__device__ float g_WprojT[CDIM * CDIM]; // (W_proj^T, tf32-rounded)

// ---------------------------------------------------------------------------
// Portable tensor-core helpers (sm_80+ mma.sync — no 'a'-suffix features)
// ---------------------------------------------------------------------------
__device__ __forceinline__ uint32_t f2tf32(float x) {
    uint32_t u;
    asm("cvt.rna.tf32.f32 %0, %1;" : "=r"(u) : "f"(x));
    return u;
}

#define MMA_TF32(d, a, b)                                                        \
    asm volatile(                                                                \
        "mma.sync.aligned.m16n8k8.row.col.f32.tf32.tf32.f32 "                    \
        "{%0,%1,%2,%3}, {%4,%5,%6,%7}, {%8,%9}, {%0,%1,%2,%3};"                  \
        : "+f"((d)[0]), "+f"((d)[1]), "+f"((d)[2]), "+f"((d)[3])                 \
        : "r"((a)[0]), "r"((a)[1]), "r"((a)[2]), "r"((a)[3]),                    \
          "r"((b)[0]), "r"((b)[1]))

// ---------------------------------------------------------------------------
// One-shot weight transposes + tf32 pre-round: out[N,K] = rna(in[K,N]^T).
// ---------------------------------------------------------------------------
__global__ __launch_bounds__(256) void transpose32(const float* __restrict__ in,
                                                   float* __restrict__ out,
                                                   int R, int C) {
    __shared__ float tile[32][33];
    const int c0 = blockIdx.x * 32, r0 = blockIdx.y * 32;
    const int tx = threadIdx.x & 31, ty = threadIdx.x >> 5;
#pragma unroll
    for (int i = 0; i < 4; i++) {
        int r = ty + i * 8;
        tile[r][tx] = in[(size_t)(r0 + r) * C + c0 + tx];
    }
    __syncthreads();
#pragma unroll
    for (int i = 0; i < 4; i++) {
        int r = ty + i * 8;
        out[(size_t)(c0 + r) * R + r0 + tx] =
            __uint_as_float(f2tf32(tile[tx][r]));
    }
}

// ---------------------------------------------------------------------------
// tf32 mma.sync GEMM, double-buffered smem, ONE barrier per K chunk.
// Staging restructured: ALL 8 LDG.128 issued back-to-back into registers
// (MLP=8), then cvt+STS.128. Bit-exact vs R11.
// MODE 0: QKV epilogue scatter -> g_Q/g_K/g_V;  MODE 1: plain out.
// ---------------------------------------------------------------------------
#define SSTR 36
#define MMT (128 * SSTR)
#define MM_SMEM (4 * MMT * 4)

template <int MODE, bool CVT_A>
__global__ __launch_bounds__(256, 2)
void mm_tf32(const float* __restrict__ A, const float* __restrict__ Bt,
             const float* __restrict__ bias, float* __restrict__ out) {
    extern __shared__ uint32_t gsm[];   // [A0 | B0 | A1 | B1]

    const int t = threadIdx.x;
    const int m0 = blockIdx.y * 128;
    const int n0 = blockIdx.x * 128;
    const int lane = t & 31, w = t >> 5;
    const int wr = w >> 2, wc = w & 3;

    float d[4][4][4];
#pragma unroll
    for (int i = 0; i < 4; i++)
#pragma unroll
        for (int j = 0; j < 4; j++)
#pragma unroll
            for (int e = 0; e < 4; e++) d[i][j][e] = 0.f;

    const int gr = t >> 3;
    const int gc4 = (t & 7) * 4;
    const float* Ap = A + (size_t)(m0 + gr) * CDIM + gc4;
    const float* Bp = Bt + (size_t)(n0 + gr) * CDIM + gc4;

    const int ar = wr * 64 + (lane >> 2);
    const int ac = lane & 3;
    const int br = wc * 32 + (lane >> 2);

    for (int k0 = 0; k0 < CDIM; k0 += 32) {
        const int st = (k0 >> 5) & 1;
        uint32_t* As = gsm + st * 2 * MMT;
        uint32_t* Bs = As + MMT;

        // Phase 1: batch ALL global loads (8 LDG.128 in flight)
        float4 va[4], vb[4];
#pragma unroll
        for (int p = 0; p < 4; p++)
            va[p] = *(const float4*)(Ap + (size_t)(p * 32) * CDIM + k0);
#pragma unroll
        for (int p = 0; p < 4; p++)
            vb[p] = *(const float4*)(Bp + (size_t)(p * 32) * CDIM + k0);

        // Phase 2: convert + store
#pragma unroll
        for (int p = 0; p < 4; p++) {
            const int row = gr + p * 32;
            uint4 ua;
            if (CVT_A) {
                ua.x = f2tf32(va[p].x); ua.y = f2tf32(va[p].y);
                ua.z = f2tf32(va[p].z); ua.w = f2tf32(va[p].w);
            } else {
                ua.x = __float_as_uint(va[p].x); ua.y = __float_as_uint(va[p].y);
                ua.z = __float_as_uint(va[p].z); ua.w = __float_as_uint(va[p].w);
            }
            uint4 ub;  // pre-rounded
            ub.x = __float_as_uint(vb[p].x); ub.y = __float_as_uint(vb[p].y);
            ub.z = __float_as_uint(vb[p].z); ub.w = __float_as_uint(vb[p].w);
            *(uint4*)&As[row * SSTR + gc4] = ua;
            *(uint4*)&Bs[row * SSTR + gc4] = ub;
        }
        __syncthreads();

#pragma unroll
        for (int ks = 0; ks < 4; ks++) {
            const int kk = ks * 8 + ac;
            uint32_t a[4][4], b[4][2];
#pragma unroll
            for (int i = 0; i < 4; i++) {
                const int r = (ar + i * 16) * SSTR;
                a[i][0] = As[r + kk];
                a[i][1] = As[r + 8 * SSTR + kk];
                a[i][2] = As[r + kk + 4];
                a[i][3] = As[r + 8 * SSTR + kk + 4];
            }
#pragma unroll
            for (int j = 0; j < 4; j++) {
                const int r = (br + j * 8) * SSTR;
                b[j][0] = Bs[r + kk];
                b[j][1] = Bs[r + kk + 4];
            }
#pragma unroll
            for (int i = 0; i < 4; i++)
#pragma unroll
                for (int j = 0; j < 4; j++) MMA_TF32(d[i][j], a[i], b[j]);
        }
    }

    const int r0 = lane >> 2, c0 = (lane & 3) * 2;
#pragma unroll
    for (int i = 0; i < 4; i++) {
        const int gmA = m0 + wr * 64 + i * 16 + r0;
        const int gmB = gmA + 8;
#pragma unroll
        for (int j = 0; j < 4; j++) {
            const int gn = n0 + wc * 32 + j * 8 + c0;
            const float bx = bias[gn], by = bias[gn + 1];
            float2 vA = make_float2(d[i][j][0] + bx, d[i][j][1] + by);
            float2 vB = make_float2(d[i][j][2] + bx, d[i][j][3] + by);
            if (MODE == 0) {
                const int which = gn >> 10;
                const int c = gn & 1023;
                const int h = c >> 6, d0 = c & 63;
                float* base = (which == 0) ? g_Q : ((which == 1) ? g_K : g_V);
                const int bA = gmA >> 11, tA = gmA & 2047;
                const int bB = gmB >> 11, tB = gmB & 2047;
                *(float2*)(base + ((size_t)(bA * NH + h) * TLEN + tA) * HD + d0) = vA;
                *(float2*)(base + ((size_t)(bB * NH + h) * TLEN + tB) * HD + d0) = vB;
            } else {
                *(float2*)(out + (size_t)gmA * CDIM + gn) = vA;
                *(float2*)(out + (size_t)gmB * CDIM + gn) = vB;
            }
        }
    }
}

// ---------------------------------------------------------------------------
// Tensor-core flash attention v7 (causal, tf32 mma.sync).
// CHANGE vs R11: K/V staging batches LDGs (two phases of 8 LDG.128 in flight)
// before any STS — kills serial per-load latency exposure. Bit-exact.
// ---------------------------------------------------------------------------
#define SA 68
#define ATTN_SMEM (2 * 64 * SA * 4)

__global__ __launch_bounds__(128) void attn_mma() {
    extern __shared__ uint32_t smw[];
    uint32_t* Ks = smw;               // 64 x SA (also Q staging pre-loop)
    uint32_t* Vs = smw + 64 * SA;     // 64 x SA  (Vs[key][d], row-major)

    const int t = threadIdx.x;
    const int lane = t & 31, w = t >> 5;
    const int qi = (gridDim.x - 1) - blockIdx.x;  // heavy tiles first
    const int bh = blockIdx.y;
    const int q0 = qi * 64;

    const float* Qg = g_Q + (size_t)bh * TLEN * HD;
    const float* Kg = g_K + (size_t)bh * TLEN * HD;
    const float* Vg = g_V + (size_t)bh * TLEN * HD;

    const int r0w = w * 16 + (lane >> 2);
    const int abase = r0w * SA;
    const int lk = lane & 3;
    const int src0 = (lane & 28) + ((lane >> 1) & 1);
    const int src1 = src0 + 2;
    const bool oddl = lane & 1;

    // Stage Q (batched: 8 LDG.128 in flight), then hoist frags to registers.
    {
        float4 qv[8];
#pragma unroll
        for (int it = 0; it < 8; it++) {
            const int i = it * 128 + t;
            qv[it] = *(const float4*)(Qg + (size_t)(q0 + (i >> 4)) * HD +
                                      (i & 15) * 4);
        }
#pragma unroll
        for (int it = 0; it < 8; it++) {
            const int i = it * 128 + t;
            const int row = i >> 4, c4 = (i & 15) * 4;
            uint4 u;
            u.x = f2tf32(qv[it].x * 0.125f);
            u.y = f2tf32(qv[it].y * 0.125f);
            u.z = f2tf32(qv[it].z * 0.125f);
            u.w = f2tf32(qv[it].w * 0.125f);
            *(uint4*)&Ks[row * SA + c4] = u;
        }
    }
    __syncthreads();
    uint32_t qf[8][4];
#pragma unroll
    for (int ks = 0; ks < 8; ks++) {
        const int kk = ks * 8 + lk;
        qf[ks][0] = Ks[abase + kk];
        qf[ks][1] = Ks[abase + 8 * SA + kk];
        qf[ks][2] = Ks[abase + kk + 4];
        qf[ks][3] = Ks[abase + 8 * SA + kk + 4];
    }

    float o[8][4];
#pragma unroll
    for (int j = 0; j < 8; j++)
#pragma unroll
        for (int e = 0; e < 4; e++) o[j][e] = 0.f;
    float m0 = -1e30f, m1 = -1e30f, l0 = 0.f, l1 = 0.f;

    for (int kt = 0; kt <= qi; kt++) {
        const int k0 = kt * 64;
        __syncthreads();  // Ks/Vs free of prior readers (incl. Q frag loads)

        // Staging, batched: phase A (its 0..3), phase B (its 4..7);
        // each phase has 8 LDG.128 (4 K + 4 V) in flight before any STS.
#pragma unroll
        for (int half = 0; half < 2; half++) {
            float4 kr[4], vr[4];
#pragma unroll
            for (int it = 0; it < 4; it++) {
                const int i = (half * 4 + it) * 128 + t;
                const int row = i >> 4, c4 = (i & 15) * 4;
                kr[it] = *(const float4*)(Kg + (size_t)(k0 + row) * HD + c4);
                vr[it] = *(const float4*)(Vg + (size_t)(k0 + row) * HD + c4);
            }
#pragma unroll
            for (int it = 0; it < 4; it++) {
                const int i = (half * 4 + it) * 128 + t;
                const int row = i >> 4, c4 = (i & 15) * 4;
                uint4 u;
                u.x = f2tf32(kr[it].x); u.y = f2tf32(kr[it].y);
                u.z = f2tf32(kr[it].z); u.w = f2tf32(kr[it].w);
                *(uint4*)&Ks[row * SA + c4] = u;
                uint4 uv;
                uv.x = f2tf32(vr[it].x); uv.y = f2tf32(vr[it].y);
                uv.z = f2tf32(vr[it].z); uv.w = f2tf32(vr[it].w);
                *(uint4*)&Vs[row * SA + c4] = uv;
            }
        }
        __syncthreads();

        // S = (Q*scale) @ K^T   (Q from registers)
        float s[8][4];
#pragma unroll
        for (int j = 0; j < 8; j++)
#pragma unroll
            for (int e = 0; e < 4; e++) s[j][e] = 0.f;
#pragma unroll
        for (int ks = 0; ks < 8; ks++) {
            const int kk = ks * 8 + lk;
#pragma unroll
            for (int j = 0; j < 8; j++) {
                const int r = (j * 8 + (lane >> 2)) * SA;
                uint32_t b[2];
                b[0] = Ks[r + kk];
                b[1] = Ks[r + kk + 4];
                MMA_TF32(s[j], qf[ks], b);
            }
        }

        // Causal mask (diagonal tile only; uniform branch)
        if (kt == qi) {
            const int gr0 = q0 + r0w, gr1 = gr0 + 8;
#pragma unroll
            for (int j = 0; j < 8; j++) {
                const int c = k0 + j * 8 + 2 * lk;
                if (c > gr0) s[j][0] = -1e30f;
                if (c + 1 > gr0) s[j][1] = -1e30f;
                if (c > gr1) s[j][2] = -1e30f;
                if (c + 1 > gr1) s[j][3] = -1e30f;
            }
        }

        // Online softmax: rows r0w (c0,c1) and r0w+8 (c2,c3)
        float tm0 = -1e30f, tm1 = -1e30f;
#pragma unroll
        for (int j = 0; j < 8; j++) {
            tm0 = fmaxf(tm0, fmaxf(s[j][0], s[j][1]));
            tm1 = fmaxf(tm1, fmaxf(s[j][2], s[j][3]));
        }
        tm0 = fmaxf(tm0, __shfl_xor_sync(0xffffffffu, tm0, 1));
        tm0 = fmaxf(tm0, __shfl_xor_sync(0xffffffffu, tm0, 2));
        tm1 = fmaxf(tm1, __shfl_xor_sync(0xffffffffu, tm1, 1));
        tm1 = fmaxf(tm1, __shfl_xor_sync(0xffffffffu, tm1, 2));

        const float mn0 = fmaxf(m0, tm0), mn1 = fmaxf(m1, tm1);
        const float al0 = __expf(m0 - mn0), al1 = __expf(m1 - mn1);
        m0 = mn0; m1 = mn1;

        float rs0 = 0.f, rs1 = 0.f;
#pragma unroll
        for (int j = 0; j < 8; j++) {
            s[j][0] = __expf(s[j][0] - mn0); rs0 += s[j][0];
            s[j][1] = __expf(s[j][1] - mn0); rs0 += s[j][1];
            s[j][2] = __expf(s[j][2] - mn1); rs1 += s[j][2];
            s[j][3] = __expf(s[j][3] - mn1); rs1 += s[j][3];
        }
        rs0 += __shfl_xor_sync(0xffffffffu, rs0, 1);
        rs0 += __shfl_xor_sync(0xffffffffu, rs0, 2);
        rs1 += __shfl_xor_sync(0xffffffffu, rs1, 1);
        rs1 += __shfl_xor_sync(0xffffffffu, rs1, 2);
        l0 = l0 * al0 + rs0;
        l1 = l1 * al1 + rs1;
#pragma unroll
        for (int j = 0; j < 8; j++) {
            o[j][0] *= al0; o[j][1] *= al0;
            o[j][2] *= al1; o[j][3] *= al1;
        }

        // O += P @ V. P A-frags from s C-frags via in-register permute.
#pragma unroll
        for (int ks = 0; ks < 8; ks++) {
            float v00 = __shfl_sync(0xffffffffu, s[ks][0], src0);
            float v01 = __shfl_sync(0xffffffffu, s[ks][1], src0);
            float v20 = __shfl_sync(0xffffffffu, s[ks][2], src0);
            float v21 = __shfl_sync(0xffffffffu, s[ks][3], src0);
            float v0b = __shfl_sync(0xffffffffu, s[ks][0], src1);
            float v1b = __shfl_sync(0xffffffffu, s[ks][1], src1);
            float v2b = __shfl_sync(0xffffffffu, s[ks][2], src1);
            float v3b = __shfl_sync(0xffffffffu, s[ks][3], src1);
            uint32_t a[4];
            a[0] = f2tf32(oddl ? v01 : v00);
            a[1] = f2tf32(oddl ? v21 : v20);
            a[2] = f2tf32(oddl ? v1b : v0b);
            a[3] = f2tf32(oddl ? v3b : v2b);
            const int vr0 = (ks * 8 + lk) * SA;
            const int vr1 = (ks * 8 + lk + 4) * SA;
#pragma unroll
            for (int j = 0; j < 8; j++) {
                const int dcol = j * 8 + (lane >> 2);
                uint32_t b[2];
                b[0] = Vs[vr0 + dcol];
                b[1] = Vs[vr1 + dcol];
                MMA_TF32(o[j], a, b);
            }
        }
    }

    // Epilogue -> g_att [B,T,C], tf32 pre-rounded (proj skips its A cvt)
    const float inv0 = 1.f / l0, inv1 = 1.f / l1;
    const int b = bh >> 4, h = bh & 15;
    const int gr0 = q0 + r0w, gr1 = gr0 + 8;
    float* o0 = g_att + ((size_t)(b * TLEN + gr0)) * CDIM + h * HD;
    float* o1 = g_att + ((size_t)(b * TLEN + gr1)) * CDIM + h * HD;
#pragma unroll
    for (int j = 0; j < 8; j++) {
        const int c = j * 8 + 2 * lk;
        *(float2*)(o0 + c) = make_float2(__uint_as_float(f2tf32(o[j][0] * inv0)),
                                         __uint_as_float(f2tf32(o[j][1] * inv0)));
        *(float2*)(o1 + c) = make_float2(__uint_as_float(f2tf32(o[j][2] * inv1)),
                                         __uint_as_float(f2tf32(o[j][3] * inv1)));
    }
}

// ---------------------------------------------------------------------------
extern "C" void kernel_launch(void* const* d_in, const int* in_sizes, int n_in,
                              void* d_out, int out_size) {
    const float* x = (const float*)d_in[0];
    const float* W_qkv = (const float*)d_in[1];
    const float* b_qkv = (const float*)d_in[2];
    const float* W_proj = (const float*)d_in[3];
    const float* b_proj = (const float*)d_in[4];
    float* out = (float*)d_out;

    float *wqkvT = nullptr, *wprojT = nullptr, *attp = nullptr;
    cudaGetSymbolAddress((void**)&wqkvT, g_WqkvT);
    cudaGetSymbolAddress((void**)&wprojT, g_WprojT);
    cudaGetSymbolAddress((void**)&attp, g_att);

    cudaFuncSetAttribute(attn_mma, cudaFuncAttributeMaxDynamicSharedMemorySize,
                         ATTN_SMEM);
    cudaFuncSetAttribute(mm_tf32<0, true>,
                         cudaFuncAttributeMaxDynamicSharedMemorySize, MM_SMEM);
    cudaFuncSetAttribute(mm_tf32<1, false>,
                         cudaFuncAttributeMaxDynamicSharedMemorySize, MM_SMEM);

    transpose32<<<dim3(N3 / 32, CDIM / 32), 256>>>(W_qkv, wqkvT, CDIM, N3);
    transpose32<<<dim3(CDIM / 32, CDIM / 32), 256>>>(W_proj, wprojT, CDIM, CDIM);

    mm_tf32<0, true><<<dim3(N3 / 128, BT / 128), 256, MM_SMEM>>>(
        x, wqkvT, b_qkv, nullptr);

    attn_mma<<<dim3(TLEN / 64, BSZ * NH), 128, ATTN_SMEM>>>();

    mm_tf32<1, false><<<dim3(CDIM / 128, BT / 128), 256, MM_SMEM>>>(
        attp, wprojT, b_proj, out);
}